// round 11
// baseline (speedup 1.0000x reference)
#include <cuda_runtime.h>
#include <math.h>
#include <stdint.h>

// Problem constants
#define BB   8
#define CC   512
#define NN   4096            // H*W
#define MM   (BB*NN)         // 32768 tokens
#define NHH  8
#define DDIM 64
#define EPSV 1e-5f
#define SCALEV 0.125f        // 64^-0.5

#define MODE_PLAIN 0
#define MODE_ROPE  1
#define MODE_OUT   2

// Scratch (device globals; container memory is tight: 5 big buffers, AO aliases kvln)
__device__ float g_big [5][MM*CC];  // 0:qln 1:kvln/AO 2:Q 3:K 4:V
__device__ float g_rope[NN*32*2];   // [n][p][{sin,cos}]
__device__ float g_Wr  [4][CC*CC];  // tf32-rounded weights

// ===========================================================================
// helpers
// ===========================================================================
__device__ __forceinline__ uint32_t smem_u32(const void* p) {
    uint32_t a;
    asm("{ .reg .u64 t; cvta.to.shared.u64 t, %1; cvt.u32.u64 %0, t; }" : "=r"(a) : "l"(p));
    return a;
}
__device__ __forceinline__ float round_tf32(float x) {
    uint32_t r;
    asm("cvt.rna.tf32.f32 %0, %1;" : "=r"(r) : "f"(x));
    return __uint_as_float(r);
}
#define CP_ASYNC16(dst, src) \
    asm volatile("cp.async.cg.shared.global [%0], [%1], 16;" :: "r"(dst), "l"(src))
#define CP_COMMIT() asm volatile("cp.async.commit_group;" ::: "memory")

#define LDMX4(r0, r1, r2, r3, addr) \
    asm volatile("ldmatrix.sync.aligned.m8n8.x4.shared.b16 {%0,%1,%2,%3}, [%4];" \
        : "=r"(r0), "=r"(r1), "=r"(r2), "=r"(r3) : "r"(addr))

#define MMA_TF32(d, a, b0v, b1v) \
    asm volatile("mma.sync.aligned.m16n8k8.row.col.f32.tf32.tf32.f32 " \
        "{%0,%1,%2,%3}, {%4,%5,%6,%7}, {%8,%9}, {%0,%1,%2,%3};" \
        : "+f"((d)[0]), "+f"((d)[1]), "+f"((d)[2]), "+f"((d)[3]) \
        : "r"((a)[0]), "r"((a)[1]), "r"((a)[2]), "r"((a)[3]), "r"(b0v), "r"(b1v))

// SW128 swizzle on a byte offset relative to a 1024B-aligned tile base
#define SWZ(o) ((o) ^ (((o) >> 3) & 0x70))

// ===========================================================================
// LayerNorm over C at each spatial position. NCHW in, (B*N, C) out (tf32-rounded).
// ===========================================================================
__global__ void __launch_bounds__(256) ln_kernel(const float* __restrict__ x,
                                                 const float* __restrict__ g,
                                                 const float* __restrict__ bln,
                                                 float* __restrict__ out)
{
    __shared__ float tile[CC][17];
    __shared__ float s_mu[16], s_rs[16];

    int m0   = blockIdx.x * 16;
    int bimg = m0 / NN;
    int n0   = m0 % NN;
    const float* xb = x + (size_t)bimg * CC * NN + n0;

    for (int idx = threadIdx.x; idx < CC * 16; idx += 256) {
        int c = idx >> 4, p = idx & 15;
        tile[c][p] = xb[(size_t)c * NN + p];
    }
    __syncthreads();

    int p = threadIdx.x >> 4;
    int l = threadIdx.x & 15;
    float sum = 0.f, sq = 0.f;
    #pragma unroll
    for (int i = 0; i < 32; i++) {
        float v = tile[l + 16 * i][p];
        sum += v; sq += v * v;
    }
    #pragma unroll
    for (int o = 8; o > 0; o >>= 1) {
        sum += __shfl_xor_sync(0xffffffffu, sum, o);
        sq  += __shfl_xor_sync(0xffffffffu, sq,  o);
    }
    if (l == 0) {
        float mu  = sum * (1.f / 512.f);
        float var = sq * (1.f / 512.f) - mu * mu;
        s_mu[p] = mu;
        s_rs[p] = rsqrtf(var + EPSV);
    }
    __syncthreads();

    // vectorized store: each thread emits one float4 run along c
    for (int idx = threadIdx.x; idx < CC * 16 / 4; idx += 256) {
        int pp = idx >> 7, c4 = (idx & 127) * 4;
        float mu = s_mu[pp], rs = s_rs[pp];
        float4 v;
        v.x = round_tf32((tile[c4+0][pp] - mu) * rs * g[c4+0] + bln[c4+0]);
        v.y = round_tf32((tile[c4+1][pp] - mu) * rs * g[c4+1] + bln[c4+1]);
        v.z = round_tf32((tile[c4+2][pp] - mu) * rs * g[c4+2] + bln[c4+2]);
        v.w = round_tf32((tile[c4+3][pp] - mu) * rs * g[c4+3] + bln[c4+3]);
        *(float4*)(out + (size_t)(m0 + pp) * CC + c4) = v;
    }
}

// ===========================================================================
// prep: weight rounding (4*CC*CC) + RoPE table (NN*32) fused in one launch
// so gemm_qkv lands at captured launch index 3.
// ===========================================================================
#define WELEMS (4 * CC * CC)
__global__ void __launch_bounds__(256) prep_kernel(
    const float* __restrict__ w0, const float* __restrict__ w1,
    const float* __restrict__ w2, const float* __restrict__ w3,
    float* __restrict__ dst, float* __restrict__ rope)
{
    int idx = blockIdx.x * 256 + threadIdx.x;
    if (idx < WELEMS) {
        int m = idx >> 18;
        int o = idx & (CC * CC - 1);
        const float* src = (m == 0) ? w0 : (m == 1) ? w1 : (m == 2) ? w2 : w3;
        dst[idx] = round_tf32(src[o]);
    } else if (idx < WELEMS + NN * 32) {
        int t = idx - WELEMS;
        int n = t >> 5, pp = t & 31;
        float inv = 1.f / powf(10000.f, (float)(2 * pp) / 64.f);
        float ang = (float)n * inv;
        rope[t * 2]     = sinf(ang);
        rope[t * 2 + 1] = cosf(ang);
    }
}

// ===========================================================================
// tf32 tensor-core GEMM core: C[m,n] = sum_k A[m,k]*W[n,k] + bias[n]
// M=32768, N=512, K=512.  CTA 128x256, 16 warps (4x4 of 32x64), BK=32,
// 3-stage cp.async -> SW128 smem -> ldmatrix.x4 -> mma.sync tf32.
// 512 threads @ <=128 regs/thread (acc 64 + frags 24 + addressing).
// Latency hiding now comes from 4 warps/SMSP, not intra-warp double-buffering.
// ===========================================================================
#define BM 128
#define BN 256
#define BK 32
#define KITERS 16
#define STAGES 3
#define STAGE_A (BM * BK * 4)                  // 16384
#define STAGE_B (BN * BK * 4)                  // 32768
#define STAGE_BYTES (STAGE_A + STAGE_B)        // 49152
#define GEMM_SMEM (STAGES * STAGE_BYTES)       // 147456
#define TROW 132                               // transpose row stride (floats)

__device__ __forceinline__ void gemm_core(
    char* smem,
    const float* __restrict__ A, const float* __restrict__ Wm,
    const float* __restrict__ bias, float* __restrict__ Cout,
    const float* __restrict__ rope, const float* __restrict__ resid,
    int mode, int m0, int n0)
{
    uint32_t sbase = smem_u32(smem);
    int tid  = threadIdx.x;
    int wid  = tid >> 5, lane = tid & 31;
    int wm   = wid & 3,  wn   = wid >> 2;      // 4 x 4 warp grid, 32x64 tiles

    const float* Arow = A  + (size_t)m0 * 512;
    const float* Brow = Wm + (size_t)n0 * 512;

    auto load_stage = [&](int kt, int slot) {
        uint32_t st = sbase + slot * STAGE_BYTES;
        int k0 = kt * BK;
        #pragma unroll
        for (int u = 0; u < 2; u++) {          // A: 128 rows x 128B = 1024 chunks
            int f = tid + u * 512;
            int r = f >> 3, q = f & 7;
            CP_ASYNC16(st + SWZ((uint32_t)(r * 128 + q * 16)),
                       Arow + (size_t)r * 512 + k0 + q * 4);
        }
        #pragma unroll
        for (int u = 0; u < 4; u++) {          // B: 256 rows x 128B = 2048 chunks
            int f = tid + u * 512;
            int r = f >> 3, q = f & 7;
            CP_ASYNC16(st + STAGE_A + SWZ((uint32_t)(r * 128 + q * 16)),
                       Brow + (size_t)r * 512 + k0 + q * 4);
        }
        CP_COMMIT();
    };

    float acc[2][8][4];
    #pragma unroll
    for (int mt = 0; mt < 2; mt++)
        #pragma unroll
        for (int nt = 0; nt < 8; nt++)
            #pragma unroll
            for (int j = 0; j < 4; j++) acc[mt][nt][j] = 0.f;

    int a_row  = wm * 32 + (lane & 15);              // + mt*16, mt<2
    int a_kb   = (lane >> 4) << 4;
    int b_row  = wn * 64 + (lane & 7) + ((lane >> 4) & 1) * 8;   // + np*16
    int b_kb   = ((lane >> 3) & 1) << 4;

    load_stage(0, 0);
    load_stage(1, 1);

    for (int kt = 0; kt < KITERS; kt++) {
        int slot = kt - (kt / 3) * 3;          // kt % 3
        if (kt < 15) asm volatile("cp.async.wait_group 1;" ::: "memory");
        else         asm volatile("cp.async.wait_group 0;" ::: "memory");
        __syncthreads();

        uint32_t sA = sbase + slot * STAGE_BYTES;
        uint32_t sB = sA + STAGE_A;

        #pragma unroll
        for (int ks = 0; ks < 4; ks++) {
            uint32_t af[2][4], bf[4][4];
            #pragma unroll
            for (int mt = 0; mt < 2; mt++) {
                uint32_t ad = sA + SWZ((uint32_t)((a_row + mt * 16) * 128 + ks * 32 + a_kb));
                LDMX4(af[mt][0], af[mt][1], af[mt][2], af[mt][3], ad);
            }
            #pragma unroll
            for (int np = 0; np < 4; np++) {
                uint32_t bd = sB + SWZ((uint32_t)((b_row + np * 16) * 128 + ks * 32 + b_kb));
                LDMX4(bf[np][0], bf[np][1], bf[np][2], bf[np][3], bd);
            }
            #pragma unroll
            for (int mt = 0; mt < 2; mt++)
                #pragma unroll
                for (int np = 0; np < 4; np++) {
                    MMA_TF32(acc[mt][2 * np],     af[mt], bf[np][0], bf[np][1]);
                    MMA_TF32(acc[mt][2 * np + 1], af[mt], bf[np][2], bf[np][3]);
                }
        }

        if (kt <= 13) {
            int kn = kt + 2;
            load_stage(kn, kn - (kn / 3) * 3);
        }
    }

    // ---------------- epilogue ----------------
    int rbase = m0 + wm * 32 + (lane >> 2);          // + mt*16 (+8)
    int cbase = n0 + wn * 64 + 2 * (lane & 3);       // + nt*8

    if (mode == MODE_OUT) {
        // bias + residual, smem-staged transpose -> coalesced NCHW float4 stores
        float* tsm = (float*)smem;                   // [128][TROW]
        int bimg  = m0 >> 12;
        int nbase = m0 & (NN - 1);
        #pragma unroll
        for (int ch = 0; ch < 2; ch++) {
            __syncthreads();
            if ((wn >> 1) == ch) {
                #pragma unroll
                for (int mt = 0; mt < 2; mt++)
                    #pragma unroll
                    for (int half = 0; half < 2; half++) {
                        int r    = rbase + mt * 16 + half * 8;
                        int mloc = r - m0;
                        const float* rr = resid + (size_t)r * 512;
                        #pragma unroll
                        for (int nt = 0; nt < 8; nt++) {
                            int c  = cbase + nt * 8;
                            int cl = (c - n0) & 127;
                            tsm[cl * TROW + mloc] =
                                acc[mt][nt][2 * half]     + bias[c]     + rr[c];
                            tsm[(cl + 1) * TROW + mloc] =
                                acc[mt][nt][2 * half + 1] + bias[c + 1] + rr[c + 1];
                        }
                    }
            }
            __syncthreads();
            #pragma unroll
            for (int u = 0; u < 8; u++) {
                int f  = tid + u * 512;              // 4096 float4s
                int cl = f >> 5, q = f & 31;
                int cg = n0 + ch * 128 + cl;
                float4 v = *(const float4*)&tsm[cl * TROW + q * 4];
                *(float4*)(Cout + (size_t)bimg * CC * NN + (size_t)cg * NN + nbase + q * 4) = v;
            }
        }
        return;
    }

    #pragma unroll
    for (int mt = 0; mt < 2; mt++) {
        int r0 = rbase + mt * 16;
        #pragma unroll
        for (int half = 0; half < 2; half++) {
            int r    = r0 + half * 8;
            int npos = r & (NN - 1);
            const float* rp = rope + (size_t)npos * 64;
            #pragma unroll
            for (int nt = 0; nt < 8; nt++) {
                int   c  = cbase + nt * 8;
                float v0 = acc[mt][nt][2 * half]     + bias[c];
                float v1 = acc[mt][nt][2 * half + 1] + bias[c + 1];

                if (mode == MODE_ROPE) {
                    int   p = (c & 63) >> 1;
                    float s = rp[2 * p], co = rp[2 * p + 1];
                    float x0 = v0, x1 = v1;
                    v0 = x0 * co - x1 * s;
                    v1 = x0 * s  + x1 * co;
                }
                float* op = Cout + (size_t)r * 512 + c;
                op[0] = v0; op[1] = v1;
            }
        }
    }
}

// Fused Q/K/V projection: blockIdx.z selects operand set (one launch, no tails)
__global__ void __launch_bounds__(512) gemm_qkv(
    const float* __restrict__ qln, const float* __restrict__ kvln,
    const float* __restrict__ Wr,
    const float* __restrict__ bq, const float* __restrict__ bk,
    const float* __restrict__ bv,
    float* __restrict__ Qb, float* __restrict__ Kb, float* __restrict__ Vb,
    const float* __restrict__ rope)
{
    extern __shared__ char smem[];
    int z = blockIdx.z;
    const float* A    = (z == 0) ? qln : kvln;
    const float* Wm   = Wr + (size_t)z * CC * CC;
    const float* bias = (z == 0) ? bq : (z == 1) ? bk : bv;
    float*       Cout = (z == 0) ? Qb : (z == 1) ? Kb : Vb;
    int mode = (z == 2) ? MODE_PLAIN : MODE_ROPE;
    gemm_core(smem, A, Wm, bias, Cout, rope, nullptr, mode,
              blockIdx.y * BM, blockIdx.x * BN);
}

// O projection (+residual, NCHW-transposed output)
__global__ void __launch_bounds__(512) gemm_out(
    const float* __restrict__ A, const float* __restrict__ Wm,
    const float* __restrict__ bias, float* __restrict__ Cout,
    const float* __restrict__ resid)
{
    extern __shared__ char smem[];
    gemm_core(smem, A, Wm, bias, Cout, nullptr, resid, MODE_OUT,
              blockIdx.y * BM, blockIdx.x * BN);
}

// ===========================================================================
// Window attention: one block per (head, window). Ws=64, D=64.
// Output rounded to tf32 grid (feeds the O-projection GEMM).
// ===========================================================================
#define ATTN_SMEM (4 * 64 * 68 * 4)

__global__ void __launch_bounds__(256) attn_kernel(
    const float* __restrict__ Q, const float* __restrict__ K,
    const float* __restrict__ V, const float* __restrict__ bt,
    float* __restrict__ O)
{
    extern __shared__ float sm[];
    float* Qs = sm;
    float* Kt = sm + 64 * 68;
    float* Vs = sm + 2 * 64 * 68;
    float* S  = sm + 3 * 64 * 68;
    __shared__ float tb[232];

    int bi  = blockIdx.x;
    int h   = bi >> 9;
    int rem = bi & 511;
    int b   = rem >> 6;
    int hn  = (rem >> 3) & 7;
    int wn  = rem & 7;
    int tid = threadIdx.x;

    for (int t = tid; t < 225; t += 256) tb[t] = bt[t * NHH + h];

    size_t base = ((size_t)b * NN) * CC + (size_t)h * DDIM;

    for (int f = tid; f < 1024; f += 256) {
        int s  = f >> 4, dq = f & 15;
        int wh = s >> 3, ww = s & 7;
        int n  = (hn * 8 + wh) * 64 + wn * 8 + ww;
        size_t ga = base + (size_t)n * CC + dq * 4;
        float4 qv = *(const float4*)(Q + ga);
        *(float4*)&Qs[s * 68 + dq * 4] = qv;
        float4 kv = *(const float4*)(K + ga);
        Kt[(dq * 4 + 0) * 68 + s] = kv.x;
        Kt[(dq * 4 + 1) * 68 + s] = kv.y;
        Kt[(dq * 4 + 2) * 68 + s] = kv.z;
        Kt[(dq * 4 + 3) * 68 + s] = kv.w;
        float4 vv = *(const float4*)(V + ga);
        *(float4*)&Vs[s * 68 + dq * 4] = vv;
    }
    __syncthreads();

    int tc = tid & 15, tr = tid >> 4;
    int r0 = tr * 4, c0 = tc * 4;

    float acc[4][4] = {};
    for (int d = 0; d < 64; d += 4) {
        float4 kf[4];
        #pragma unroll
        for (int u = 0; u < 4; u++) kf[u] = *(const float4*)&Kt[(d + u) * 68 + c0];
        #pragma unroll
        for (int ii = 0; ii < 4; ii++) {
            float4 qf = *(const float4*)&Qs[(r0 + ii) * 68 + d];
            acc[ii][0] += qf.x*kf[0].x + qf.y*kf[1].x + qf.z*kf[2].x + qf.w*kf[3].x;
            acc[ii][1] += qf.x*kf[0].y + qf.y*kf[1].y + qf.z*kf[2].y + qf.w*kf[3].y;
            acc[ii][2] += qf.x*kf[0].z + qf.y*kf[1].z + qf.z*kf[2].z + qf.w*kf[3].z;
            acc[ii][3] += qf.x*kf[0].w + qf.y*kf[1].w + qf.z*kf[2].w + qf.w*kf[3].w;
        }
    }

    #pragma unroll
    for (int ii = 0; ii < 4; ii++) {
        int i = r0 + ii; int ih = i >> 3, iw = i & 7;
        #pragma unroll
        for (int jj = 0; jj < 4; jj++) {
            int j = c0 + jj; int jh = j >> 3, jw = j & 7;
            int ridx = (ih - jh + 7) * 15 + (iw - jw + 7);
            S[i * 68 + j] = acc[ii][jj] * SCALEV + tb[ridx];
        }
    }
    __syncthreads();

    {
        int r = tid >> 2, qg = tid & 3;
        float* row = S + r * 68 + qg * 16;
        float mx = -INFINITY;
        #pragma unroll
        for (int j = 0; j < 16; j++) mx = fmaxf(mx, row[j]);
        mx = fmaxf(mx, __shfl_xor_sync(0xffffffffu, mx, 1));
        mx = fmaxf(mx, __shfl_xor_sync(0xffffffffu, mx, 2));
        float e[16], sum = 0.f;
        #pragma unroll
        for (int j = 0; j < 16; j++) { e[j] = expf(row[j] - mx); sum += e[j]; }
        sum += __shfl_xor_sync(0xffffffffu, sum, 1);
        sum += __shfl_xor_sync(0xffffffffu, sum, 2);
        float inv = 1.f / sum;
        #pragma unroll
        for (int j = 0; j < 16; j++) row[j] = e[j] * inv;
    }
    __syncthreads();

    float oacc[4][4] = {};
    for (int j = 0; j < 64; j += 4) {
        float4 vf[4];
        #pragma unroll
        for (int u = 0; u < 4; u++) vf[u] = *(const float4*)&Vs[(j + u) * 68 + c0];
        #pragma unroll
        for (int ii = 0; ii < 4; ii++) {
            float4 pf = *(const float4*)&S[(r0 + ii) * 68 + j];
            oacc[ii][0] += pf.x*vf[0].x + pf.y*vf[1].x + pf.z*vf[2].x + pf.w*vf[3].x;
            oacc[ii][1] += pf.x*vf[0].y + pf.y*vf[1].y + pf.z*vf[2].y + pf.w*vf[3].y;
            oacc[ii][2] += pf.x*vf[0].z + pf.y*vf[1].z + pf.z*vf[2].z + pf.w*vf[3].z;
            oacc[ii][3] += pf.x*vf[0].w + pf.y*vf[1].w + pf.z*vf[2].w + pf.w*vf[3].w;
        }
    }

    #pragma unroll
    for (int ii = 0; ii < 4; ii++) {
        int s  = r0 + ii;
        int wh = s >> 3, ww = s & 7;
        int n  = (hn * 8 + wh) * 64 + wn * 8 + ww;
        *(float4*)(O + base + (size_t)n * CC + c0) =
            make_float4(round_tf32(oacc[ii][0]), round_tf32(oacc[ii][1]),
                        round_tf32(oacc[ii][2]), round_tf32(oacc[ii][3]));
    }
}

// ===========================================================================
extern "C" void kernel_launch(void* const* d_in, const int* in_sizes, int n_in,
                              void* d_out, int out_size)
{
    const float* q    = (const float*)d_in[0];
    const float* kv   = (const float*)d_in[1];
    const float* g_q  = (const float*)d_in[2];
    const float* b_q  = (const float*)d_in[3];
    const float* g_kv = (const float*)d_in[4];
    const float* b_kv = (const float*)d_in[5];
    const float* Wq   = (const float*)d_in[6];
    const float* bq   = (const float*)d_in[7];
    const float* Wk   = (const float*)d_in[8];
    const float* bk   = (const float*)d_in[9];
    const float* Wv   = (const float*)d_in[10];
    const float* bv   = (const float*)d_in[11];
    const float* Wo   = (const float*)d_in[12];
    const float* bo   = (const float*)d_in[13];
    const float* bt   = (const float*)d_in[14];
    float* out = (float*)d_out;

    void *p_big, *p_rope, *p_Wr;
    cudaGetSymbolAddress(&p_big,  g_big);
    cudaGetSymbolAddress(&p_rope, g_rope);
    cudaGetSymbolAddress(&p_Wr,   g_Wr);

    float* qln  = (float*)p_big + 0 * (size_t)MM * CC;
    float* kvln = (float*)p_big + 1 * (size_t)MM * CC;
    float* Qb   = (float*)p_big + 2 * (size_t)MM * CC;
    float* Kb   = (float*)p_big + 3 * (size_t)MM * CC;
    float* Vb   = (float*)p_big + 4 * (size_t)MM * CC;
    float* AO   = kvln;                 // aliased: kvln dead after V GEMM
    float* Wr   = (float*)p_Wr;
    float* rope = (float*)p_rope;

    cudaFuncSetAttribute(attn_kernel, cudaFuncAttributeMaxDynamicSharedMemorySize, ATTN_SMEM);
    cudaFuncSetAttribute(gemm_qkv,    cudaFuncAttributeMaxDynamicSharedMemorySize, GEMM_SMEM);
    cudaFuncSetAttribute(gemm_out,    cudaFuncAttributeMaxDynamicSharedMemorySize, GEMM_SMEM);

    // launch order chosen so gemm_qkv sits at captured ncu index 3
    ln_kernel<<<MM / 16, 256>>>(q,  g_q,  b_q,  qln);                 // 0
    ln_kernel<<<MM / 16, 256>>>(kv, g_kv, b_kv, kvln);                // 1
    prep_kernel<<<(WELEMS + NN * 32 + 255) / 256, 256>>>(Wq, Wk, Wv, Wo, Wr, rope); // 2

    dim3 g_qkv(2, 256, 3);
    gemm_qkv<<<g_qkv, 512, GEMM_SMEM>>>(qln, kvln, Wr, bq, bk, bv,
                                        Qb, Kb, Vb, rope);            // 3 <- profiled

    attn_kernel<<<NHH * BB * 64, 256, ATTN_SMEM>>>(Qb, Kb, Vb, bt, AO);

    dim3 g_o(2, 256);
    gemm_out<<<g_o, 512, GEMM_SMEM>>>(AO, Wr + 3 * (size_t)CC * CC, bo, out, qln);
}

// round 12
// speedup vs baseline: 1.1717x; 1.1717x over previous
#include <cuda_runtime.h>
#include <math.h>
#include <stdint.h>

// Problem constants
#define BB   8
#define CC   512
#define NN   4096            // H*W
#define MM   (BB*NN)         // 32768 tokens
#define NHH  8
#define DDIM 64
#define EPSV 1e-5f
#define SCALEV 0.125f        // 64^-0.5

#define MODE_PLAIN 0
#define MODE_ROPE  1
#define MODE_OUT   2

// Scratch (device globals; container memory is tight: 5 big buffers, AO aliases kvln)
__device__ float g_big [5][MM*CC];  // 0:qln 1:kvln/AO 2:Q 3:K 4:V
__device__ float g_rope[NN*32*2];   // [n][p][{sin,cos}]
__device__ float g_Wr  [4][CC*CC];  // tf32-rounded weights

// ===========================================================================
// helpers
// ===========================================================================
__device__ __forceinline__ uint32_t smem_u32(const void* p) {
    uint32_t a;
    asm("{ .reg .u64 t; cvta.to.shared.u64 t, %1; cvt.u32.u64 %0, t; }" : "=r"(a) : "l"(p));
    return a;
}
__device__ __forceinline__ float round_tf32(float x) {
    uint32_t r;
    asm("cvt.rna.tf32.f32 %0, %1;" : "=r"(r) : "f"(x));
    return __uint_as_float(r);
}
#define CP_ASYNC16(dst, src) \
    asm volatile("cp.async.cg.shared.global [%0], [%1], 16;" :: "r"(dst), "l"(src))
#define CP_COMMIT() asm volatile("cp.async.commit_group;" ::: "memory")

#define LDMX4(r0, r1, r2, r3, addr) \
    asm volatile("ldmatrix.sync.aligned.m8n8.x4.shared.b16 {%0,%1,%2,%3}, [%4];" \
        : "=r"(r0), "=r"(r1), "=r"(r2), "=r"(r3) : "r"(addr))

#define MMA_TF32(d, a, b0v, b1v) \
    asm volatile("mma.sync.aligned.m16n8k8.row.col.f32.tf32.tf32.f32 " \
        "{%0,%1,%2,%3}, {%4,%5,%6,%7}, {%8,%9}, {%0,%1,%2,%3};" \
        : "+f"((d)[0]), "+f"((d)[1]), "+f"((d)[2]), "+f"((d)[3]) \
        : "r"((a)[0]), "r"((a)[1]), "r"((a)[2]), "r"((a)[3]), "r"(b0v), "r"(b1v))

// SW128 swizzle on a byte offset relative to a 1024B-aligned tile base
#define SWZ(o) ((o) ^ (((o) >> 3) & 0x70))

// ===========================================================================
// LayerNorm over C at each spatial position. NCHW in, (B*N, C) out (tf32-rounded).
// ===========================================================================
__global__ void __launch_bounds__(256) ln_kernel(const float* __restrict__ x,
                                                 const float* __restrict__ g,
                                                 const float* __restrict__ bln,
                                                 float* __restrict__ out)
{
    __shared__ float tile[CC][17];
    __shared__ float s_mu[16], s_rs[16];

    int m0   = blockIdx.x * 16;
    int bimg = m0 / NN;
    int n0   = m0 % NN;
    const float* xb = x + (size_t)bimg * CC * NN + n0;

    for (int idx = threadIdx.x; idx < CC * 16; idx += 256) {
        int c = idx >> 4, p = idx & 15;
        tile[c][p] = xb[(size_t)c * NN + p];
    }
    __syncthreads();

    int p = threadIdx.x >> 4;
    int l = threadIdx.x & 15;
    float sum = 0.f, sq = 0.f;
    #pragma unroll
    for (int i = 0; i < 32; i++) {
        float v = tile[l + 16 * i][p];
        sum += v; sq += v * v;
    }
    #pragma unroll
    for (int o = 8; o > 0; o >>= 1) {
        sum += __shfl_xor_sync(0xffffffffu, sum, o);
        sq  += __shfl_xor_sync(0xffffffffu, sq,  o);
    }
    if (l == 0) {
        float mu  = sum * (1.f / 512.f);
        float var = sq * (1.f / 512.f) - mu * mu;
        s_mu[p] = mu;
        s_rs[p] = rsqrtf(var + EPSV);
    }
    __syncthreads();

    // vectorized store: each thread emits one float4 run along c
    for (int idx = threadIdx.x; idx < CC * 16 / 4; idx += 256) {
        int pp = idx >> 7, c4 = (idx & 127) * 4;
        float mu = s_mu[pp], rs = s_rs[pp];
        float4 v;
        v.x = round_tf32((tile[c4+0][pp] - mu) * rs * g[c4+0] + bln[c4+0]);
        v.y = round_tf32((tile[c4+1][pp] - mu) * rs * g[c4+1] + bln[c4+1]);
        v.z = round_tf32((tile[c4+2][pp] - mu) * rs * g[c4+2] + bln[c4+2]);
        v.w = round_tf32((tile[c4+3][pp] - mu) * rs * g[c4+3] + bln[c4+3]);
        *(float4*)(out + (size_t)(m0 + pp) * CC + c4) = v;
    }
}

// ===========================================================================
// prep: weight rounding (4*CC*CC) + RoPE table (NN*32) fused in one launch
// so gemm_qkv lands at captured launch index 3.
// ===========================================================================
#define WELEMS (4 * CC * CC)
__global__ void __launch_bounds__(256) prep_kernel(
    const float* __restrict__ w0, const float* __restrict__ w1,
    const float* __restrict__ w2, const float* __restrict__ w3,
    float* __restrict__ dst, float* __restrict__ rope)
{
    int idx = blockIdx.x * 256 + threadIdx.x;
    if (idx < WELEMS) {
        int m = idx >> 18;
        int o = idx & (CC * CC - 1);
        const float* src = (m == 0) ? w0 : (m == 1) ? w1 : (m == 2) ? w2 : w3;
        dst[idx] = round_tf32(src[o]);
    } else if (idx < WELEMS + NN * 32) {
        int t = idx - WELEMS;
        int n = t >> 5, pp = t & 31;
        float inv = 1.f / powf(10000.f, (float)(2 * pp) / 64.f);
        float ang = (float)n * inv;
        rope[t * 2]     = sinf(ang);
        rope[t * 2 + 1] = cosf(ang);
    }
}

// ===========================================================================
// tf32 tensor-core GEMM core: C[m,n] = sum_k A[m,k]*W[n,k] + bias[n]
// M=32768, N=512, K=512.  CTA 128x128, 4 warps (2x2 of 64x64), BK=32,
// 3-stage cp.async -> SW128 smem -> ldmatrix.x4 -> mma.sync tf32,
// fragment double-buffered.  128 threads, __launch_bounds__(128, 2):
// <=255 regs and TWO CTAs per SM, so one CTA's barrier/wait stalls are
// covered by the other CTA's MMA issue (single-CTA barriers were the
// R10/R11 utilization ceiling).
// ===========================================================================
#define BM 128
#define BN 128
#define BK 32
#define KITERS 16
#define STAGES 3
#define STAGE_A (BM * BK * 4)                  // 16384
#define STAGE_B (BN * BK * 4)                  // 16384
#define STAGE_BYTES (STAGE_A + STAGE_B)        // 32768
#define GEMM_SMEM (STAGES * STAGE_BYTES)       // 98304  (2 CTAs/SM)
#define TROW 132                               // transpose row stride (floats)

__device__ __forceinline__ void gemm_core(
    char* smem,
    const float* __restrict__ A, const float* __restrict__ Wm,
    const float* __restrict__ bias, float* __restrict__ Cout,
    const float* __restrict__ rope, const float* __restrict__ resid,
    int mode, int m0, int n0)
{
    uint32_t sbase = smem_u32(smem);
    int tid  = threadIdx.x;
    int wid  = tid >> 5, lane = tid & 31;
    int wm   = wid & 1,  wn   = wid >> 1;      // 2 x 2 warp grid, 64x64 tiles

    const float* Arow = A  + (size_t)m0 * 512;
    const float* Brow = Wm + (size_t)n0 * 512;

    auto load_stage = [&](int kt, int slot) {
        uint32_t st = sbase + slot * STAGE_BYTES;
        int k0 = kt * BK;
        #pragma unroll
        for (int u = 0; u < 8; u++) {          // A: 128 rows x 128B = 1024 chunks
            int f = tid + u * 128;
            int r = f >> 3, q = f & 7;
            CP_ASYNC16(st + SWZ((uint32_t)(r * 128 + q * 16)),
                       Arow + (size_t)r * 512 + k0 + q * 4);
        }
        #pragma unroll
        for (int u = 0; u < 8; u++) {          // B: 128 rows x 128B = 1024 chunks
            int f = tid + u * 128;
            int r = f >> 3, q = f & 7;
            CP_ASYNC16(st + STAGE_A + SWZ((uint32_t)(r * 128 + q * 16)),
                       Brow + (size_t)r * 512 + k0 + q * 4);
        }
        CP_COMMIT();
    };

    float acc[4][8][4];
    #pragma unroll
    for (int mt = 0; mt < 4; mt++)
        #pragma unroll
        for (int nt = 0; nt < 8; nt++)
            #pragma unroll
            for (int j = 0; j < 4; j++) acc[mt][nt][j] = 0.f;

    int a_row  = wm * 64 + (lane & 15);              // + mt*16
    int a_kb   = (lane >> 4) << 4;
    int b_row  = wn * 64 + (lane & 7) + ((lane >> 4) & 1) * 8;   // + np*16
    int b_kb   = ((lane >> 3) & 1) << 4;

    load_stage(0, 0);
    load_stage(1, 1);

    uint32_t af[2][4][4], bf[2][4][4];

    for (int kt = 0; kt < KITERS; kt++) {
        int slot = kt - (kt / 3) * 3;          // kt % 3
        if (kt < 15) asm volatile("cp.async.wait_group 1;" ::: "memory");
        else         asm volatile("cp.async.wait_group 0;" ::: "memory");
        __syncthreads();

        uint32_t sA = sbase + slot * STAGE_BYTES;
        uint32_t sB = sA + STAGE_A;

        // prime fragments for ks=0
        #pragma unroll
        for (int mt = 0; mt < 4; mt++) {
            uint32_t ad = sA + SWZ((uint32_t)((a_row + mt * 16) * 128 + a_kb));
            LDMX4(af[0][mt][0], af[0][mt][1], af[0][mt][2], af[0][mt][3], ad);
        }
        #pragma unroll
        for (int np = 0; np < 4; np++) {
            uint32_t bd = sB + SWZ((uint32_t)((b_row + np * 16) * 128 + b_kb));
            LDMX4(bf[0][np][0], bf[0][np][1], bf[0][np][2], bf[0][np][3], bd);
        }

        #pragma unroll
        for (int ks = 0; ks < 4; ks++) {
            int cur = ks & 1, nxt = cur ^ 1;
            if (ks < 3) {   // prefetch ks+1 fragments while ks MMAs issue
                #pragma unroll
                for (int mt = 0; mt < 4; mt++) {
                    uint32_t ad = sA + SWZ((uint32_t)((a_row + mt * 16) * 128 + (ks + 1) * 32 + a_kb));
                    LDMX4(af[nxt][mt][0], af[nxt][mt][1], af[nxt][mt][2], af[nxt][mt][3], ad);
                }
                #pragma unroll
                for (int np = 0; np < 4; np++) {
                    uint32_t bd = sB + SWZ((uint32_t)((b_row + np * 16) * 128 + (ks + 1) * 32 + b_kb));
                    LDMX4(bf[nxt][np][0], bf[nxt][np][1], bf[nxt][np][2], bf[nxt][np][3], bd);
                }
            }
            #pragma unroll
            for (int mt = 0; mt < 4; mt++)
                #pragma unroll
                for (int np = 0; np < 4; np++) {
                    MMA_TF32(acc[mt][2 * np],     af[cur][mt], bf[cur][np][0], bf[cur][np][1]);
                    MMA_TF32(acc[mt][2 * np + 1], af[cur][mt], bf[cur][np][2], bf[cur][np][3]);
                }
        }

        if (kt <= 13) {
            int kn = kt + 2;
            load_stage(kn, kn - (kn / 3) * 3);
        }
    }

    // ---------------- epilogue ----------------
    int rbase = m0 + wm * 64 + (lane >> 2);          // + mt*16 (+8)
    int cbase = n0 + wn * 64 + 2 * (lane & 3);       // + nt*8

    if (mode == MODE_OUT) {
        // bias + residual, smem-staged transpose -> coalesced NCHW float4 stores
        float* tsm = (float*)smem;                   // [128][TROW] = 67.6 KB
        int bimg  = m0 >> 12;
        int nbase = m0 & (NN - 1);
        __syncthreads();
        #pragma unroll
        for (int mt = 0; mt < 4; mt++)
            #pragma unroll
            for (int half = 0; half < 2; half++) {
                int r    = rbase + mt * 16 + half * 8;
                int mloc = r - m0;
                const float* rr = resid + (size_t)r * 512;
                #pragma unroll
                for (int nt = 0; nt < 8; nt++) {
                    int c  = cbase + nt * 8;
                    int cl = c - n0;
                    tsm[cl * TROW + mloc] =
                        acc[mt][nt][2 * half]     + bias[c]     + rr[c];
                    tsm[(cl + 1) * TROW + mloc] =
                        acc[mt][nt][2 * half + 1] + bias[c + 1] + rr[c + 1];
                }
            }
        __syncthreads();
        #pragma unroll
        for (int u = 0; u < 32; u++) {
            int f  = tid + u * 128;                  // 4096 float4s
            int cl = f >> 5, q = f & 31;
            int cg = n0 + cl;
            float4 v = *(const float4*)&tsm[cl * TROW + q * 4];
            *(float4*)(Cout + (size_t)bimg * CC * NN + (size_t)cg * NN + nbase + q * 4) = v;
        }
        return;
    }

    #pragma unroll
    for (int mt = 0; mt < 4; mt++) {
        int r0 = rbase + mt * 16;
        #pragma unroll
        for (int half = 0; half < 2; half++) {
            int r    = r0 + half * 8;
            int npos = r & (NN - 1);
            const float* rp = rope + (size_t)npos * 64;
            #pragma unroll
            for (int nt = 0; nt < 8; nt++) {
                int   c  = cbase + nt * 8;
                float v0 = acc[mt][nt][2 * half]     + bias[c];
                float v1 = acc[mt][nt][2 * half + 1] + bias[c + 1];

                if (mode == MODE_ROPE) {
                    int   p = (c & 63) >> 1;
                    float s = rp[2 * p], co = rp[2 * p + 1];
                    float x0 = v0, x1 = v1;
                    v0 = x0 * co - x1 * s;
                    v1 = x0 * s  + x1 * co;
                }
                float* op = Cout + (size_t)r * 512 + c;
                op[0] = v0; op[1] = v1;
            }
        }
    }
}

// Fused Q/K/V projection: blockIdx.z selects operand set (one launch, no tails)
__global__ void __launch_bounds__(128, 2) gemm_qkv(
    const float* __restrict__ qln, const float* __restrict__ kvln,
    const float* __restrict__ Wr,
    const float* __restrict__ bq, const float* __restrict__ bk,
    const float* __restrict__ bv,
    float* __restrict__ Qb, float* __restrict__ Kb, float* __restrict__ Vb,
    const float* __restrict__ rope)
{
    extern __shared__ char smem[];
    int z = blockIdx.z;
    const float* A    = (z == 0) ? qln : kvln;
    const float* Wm   = Wr + (size_t)z * CC * CC;
    const float* bias = (z == 0) ? bq : (z == 1) ? bk : bv;
    float*       Cout = (z == 0) ? Qb : (z == 1) ? Kb : Vb;
    int mode = (z == 2) ? MODE_PLAIN : MODE_ROPE;
    gemm_core(smem, A, Wm, bias, Cout, rope, nullptr, mode,
              blockIdx.y * BM, blockIdx.x * BN);
}

// O projection (+residual, NCHW-transposed output)
__global__ void __launch_bounds__(128, 2) gemm_out(
    const float* __restrict__ A, const float* __restrict__ Wm,
    const float* __restrict__ bias, float* __restrict__ Cout,
    const float* __restrict__ resid)
{
    extern __shared__ char smem[];
    gemm_core(smem, A, Wm, bias, Cout, nullptr, resid, MODE_OUT,
              blockIdx.y * BM, blockIdx.x * BN);
}

// ===========================================================================
// Window attention: one block per (head, window). Ws=64, D=64.
// Output rounded to tf32 grid (feeds the O-projection GEMM).
// ===========================================================================
#define ATTN_SMEM (4 * 64 * 68 * 4)

__global__ void __launch_bounds__(256) attn_kernel(
    const float* __restrict__ Q, const float* __restrict__ K,
    const float* __restrict__ V, const float* __restrict__ bt,
    float* __restrict__ O)
{
    extern __shared__ float sm[];
    float* Qs = sm;
    float* Kt = sm + 64 * 68;
    float* Vs = sm + 2 * 64 * 68;
    float* S  = sm + 3 * 64 * 68;
    __shared__ float tb[232];

    int bi  = blockIdx.x;
    int h   = bi >> 9;
    int rem = bi & 511;
    int b   = rem >> 6;
    int hn  = (rem >> 3) & 7;
    int wn  = rem & 7;
    int tid = threadIdx.x;

    for (int t = tid; t < 225; t += 256) tb[t] = bt[t * NHH + h];

    size_t base = ((size_t)b * NN) * CC + (size_t)h * DDIM;

    for (int f = tid; f < 1024; f += 256) {
        int s  = f >> 4, dq = f & 15;
        int wh = s >> 3, ww = s & 7;
        int n  = (hn * 8 + wh) * 64 + wn * 8 + ww;
        size_t ga = base + (size_t)n * CC + dq * 4;
        float4 qv = *(const float4*)(Q + ga);
        *(float4*)&Qs[s * 68 + dq * 4] = qv;
        float4 kv = *(const float4*)(K + ga);
        Kt[(dq * 4 + 0) * 68 + s] = kv.x;
        Kt[(dq * 4 + 1) * 68 + s] = kv.y;
        Kt[(dq * 4 + 2) * 68 + s] = kv.z;
        Kt[(dq * 4 + 3) * 68 + s] = kv.w;
        float4 vv = *(const float4*)(V + ga);
        *(float4*)&Vs[s * 68 + dq * 4] = vv;
    }
    __syncthreads();

    int tc = tid & 15, tr = tid >> 4;
    int r0 = tr * 4, c0 = tc * 4;

    float acc[4][4] = {};
    for (int d = 0; d < 64; d += 4) {
        float4 kf[4];
        #pragma unroll
        for (int u = 0; u < 4; u++) kf[u] = *(const float4*)&Kt[(d + u) * 68 + c0];
        #pragma unroll
        for (int ii = 0; ii < 4; ii++) {
            float4 qf = *(const float4*)&Qs[(r0 + ii) * 68 + d];
            acc[ii][0] += qf.x*kf[0].x + qf.y*kf[1].x + qf.z*kf[2].x + qf.w*kf[3].x;
            acc[ii][1] += qf.x*kf[0].y + qf.y*kf[1].y + qf.z*kf[2].y + qf.w*kf[3].y;
            acc[ii][2] += qf.x*kf[0].z + qf.y*kf[1].z + qf.z*kf[2].z + qf.w*kf[3].z;
            acc[ii][3] += qf.x*kf[0].w + qf.y*kf[1].w + qf.z*kf[2].w + qf.w*kf[3].w;
        }
    }

    #pragma unroll
    for (int ii = 0; ii < 4; ii++) {
        int i = r0 + ii; int ih = i >> 3, iw = i & 7;
        #pragma unroll
        for (int jj = 0; jj < 4; jj++) {
            int j = c0 + jj; int jh = j >> 3, jw = j & 7;
            int ridx = (ih - jh + 7) * 15 + (iw - jw + 7);
            S[i * 68 + j] = acc[ii][jj] * SCALEV + tb[ridx];
        }
    }
    __syncthreads();

    {
        int r = tid >> 2, qg = tid & 3;
        float* row = S + r * 68 + qg * 16;
        float mx = -INFINITY;
        #pragma unroll
        for (int j = 0; j < 16; j++) mx = fmaxf(mx, row[j]);
        mx = fmaxf(mx, __shfl_xor_sync(0xffffffffu, mx, 1));
        mx = fmaxf(mx, __shfl_xor_sync(0xffffffffu, mx, 2));
        float e[16], sum = 0.f;
        #pragma unroll
        for (int j = 0; j < 16; j++) { e[j] = expf(row[j] - mx); sum += e[j]; }
        sum += __shfl_xor_sync(0xffffffffu, sum, 1);
        sum += __shfl_xor_sync(0xffffffffu, sum, 2);
        float inv = 1.f / sum;
        #pragma unroll
        for (int j = 0; j < 16; j++) row[j] = e[j] * inv;
    }
    __syncthreads();

    float oacc[4][4] = {};
    for (int j = 0; j < 64; j += 4) {
        float4 vf[4];
        #pragma unroll
        for (int u = 0; u < 4; u++) vf[u] = *(const float4*)&Vs[(j + u) * 68 + c0];
        #pragma unroll
        for (int ii = 0; ii < 4; ii++) {
            float4 pf = *(const float4*)&S[(r0 + ii) * 68 + j];
            oacc[ii][0] += pf.x*vf[0].x + pf.y*vf[1].x + pf.z*vf[2].x + pf.w*vf[3].x;
            oacc[ii][1] += pf.x*vf[0].y + pf.y*vf[1].y + pf.z*vf[2].y + pf.w*vf[3].y;
            oacc[ii][2] += pf.x*vf[0].z + pf.y*vf[1].z + pf.z*vf[2].z + pf.w*vf[3].z;
            oacc[ii][3] += pf.x*vf[0].w + pf.y*vf[1].w + pf.z*vf[2].w + pf.w*vf[3].w;
        }
    }

    #pragma unroll
    for (int ii = 0; ii < 4; ii++) {
        int s  = r0 + ii;
        int wh = s >> 3, ww = s & 7;
        int n  = (hn * 8 + wh) * 64 + wn * 8 + ww;
        *(float4*)(O + base + (size_t)n * CC + c0) =
            make_float4(round_tf32(oacc[ii][0]), round_tf32(oacc[ii][1]),
                        round_tf32(oacc[ii][2]), round_tf32(oacc[ii][3]));
    }
}

// ===========================================================================
extern "C" void kernel_launch(void* const* d_in, const int* in_sizes, int n_in,
                              void* d_out, int out_size)
{
    const float* q    = (const float*)d_in[0];
    const float* kv   = (const float*)d_in[1];
    const float* g_q  = (const float*)d_in[2];
    const float* b_q  = (const float*)d_in[3];
    const float* g_kv = (const float*)d_in[4];
    const float* b_kv = (const float*)d_in[5];
    const float* Wq   = (const float*)d_in[6];
    const float* bq   = (const float*)d_in[7];
    const float* Wk   = (const float*)d_in[8];
    const float* bk   = (const float*)d_in[9];
    const float* Wv   = (const float*)d_in[10];
    const float* bv   = (const float*)d_in[11];
    const float* Wo   = (const float*)d_in[12];
    const float* bo   = (const float*)d_in[13];
    const float* bt   = (const float*)d_in[14];
    float* out = (float*)d_out;

    void *p_big, *p_rope, *p_Wr;
    cudaGetSymbolAddress(&p_big,  g_big);
    cudaGetSymbolAddress(&p_rope, g_rope);
    cudaGetSymbolAddress(&p_Wr,   g_Wr);

    float* qln  = (float*)p_big + 0 * (size_t)MM * CC;
    float* kvln = (float*)p_big + 1 * (size_t)MM * CC;
    float* Qb   = (float*)p_big + 2 * (size_t)MM * CC;
    float* Kb   = (float*)p_big + 3 * (size_t)MM * CC;
    float* Vb   = (float*)p_big + 4 * (size_t)MM * CC;
    float* AO   = kvln;                 // aliased: kvln dead after V GEMM
    float* Wr   = (float*)p_Wr;
    float* rope = (float*)p_rope;

    cudaFuncSetAttribute(attn_kernel, cudaFuncAttributeMaxDynamicSharedMemorySize, ATTN_SMEM);
    cudaFuncSetAttribute(gemm_qkv,    cudaFuncAttributeMaxDynamicSharedMemorySize, GEMM_SMEM);
    cudaFuncSetAttribute(gemm_out,    cudaFuncAttributeMaxDynamicSharedMemorySize, GEMM_SMEM);

    // launch order chosen so gemm_qkv sits at captured ncu index 3
    ln_kernel<<<MM / 16, 256>>>(q,  g_q,  b_q,  qln);                 // 0
    ln_kernel<<<MM / 16, 256>>>(kv, g_kv, b_kv, kvln);                // 1
    prep_kernel<<<(WELEMS + NN * 32 + 255) / 256, 256>>>(Wq, Wk, Wv, Wo, Wr, rope); // 2

    dim3 g_qkv(4, 256, 3);
    gemm_qkv<<<g_qkv, 128, GEMM_SMEM>>>(qln, kvln, Wr, bq, bk, bv,
                                        Qb, Kb, Vb, rope);            // 3 <- profiled

    attn_kernel<<<NHH * BB * 64, 256, ATTN_SMEM>>>(Qb, Kb, Vb, bt, AO);

    dim3 g_o(4, 256);
    gemm_out<<<g_o, 128, GEMM_SMEM>>>(AO, Wr + 3 * (size_t)CC * CC, bo, out, qln);
}

// round 13
// speedup vs baseline: 1.2267x; 1.0469x over previous
#include <cuda_runtime.h>
#include <math.h>
#include <stdint.h>

// Problem constants
#define BB   8
#define CC   512
#define NN   4096            // H*W
#define MM   (BB*NN)         // 32768 tokens
#define NHH  8
#define DDIM 64
#define EPSV 1e-5f
#define SCALEV 0.125f        // 64^-0.5

#define MODE_PLAIN 0
#define MODE_ROPE  1
#define MODE_OUT   2

// Scratch (device globals; container memory is tight: 5 big buffers, AO aliases kvln)
__device__ float g_big [5][MM*CC];  // 0:qln 1:kvln/AO 2:Q 3:K 4:V
__device__ float g_rope[NN*32*2];   // [n][p][{sin,cos}]
__device__ float g_Wr  [4][CC*CC];  // tf32-rounded weights

// ===========================================================================
// helpers
// ===========================================================================
__device__ __forceinline__ uint32_t smem_u32(const void* p) {
    uint32_t a;
    asm("{ .reg .u64 t; cvta.to.shared.u64 t, %1; cvt.u32.u64 %0, t; }" : "=r"(a) : "l"(p));
    return a;
}
__device__ __forceinline__ float round_tf32(float x) {
    uint32_t r;
    asm("cvt.rna.tf32.f32 %0, %1;" : "=r"(r) : "f"(x));
    return __uint_as_float(r);
}
#define CP_ASYNC16(dst, src) \
    asm volatile("cp.async.cg.shared.global [%0], [%1], 16;" :: "r"(dst), "l"(src))
#define CP_COMMIT() asm volatile("cp.async.commit_group;" ::: "memory")

#define LDMX4(r0, r1, r2, r3, addr) \
    asm volatile("ldmatrix.sync.aligned.m8n8.x4.shared.b16 {%0,%1,%2,%3}, [%4];" \
        : "=r"(r0), "=r"(r1), "=r"(r2), "=r"(r3) : "r"(addr))

#define MMA_TF32(d, a, b0v, b1v) \
    asm volatile("mma.sync.aligned.m16n8k8.row.col.f32.tf32.tf32.f32 " \
        "{%0,%1,%2,%3}, {%4,%5,%6,%7}, {%8,%9}, {%0,%1,%2,%3};" \
        : "+f"((d)[0]), "+f"((d)[1]), "+f"((d)[2]), "+f"((d)[3]) \
        : "r"((a)[0]), "r"((a)[1]), "r"((a)[2]), "r"((a)[3]), "r"(b0v), "r"(b1v))

// SW128 swizzle on a byte offset relative to a 1024B-aligned tile base
#define SWZ(o) ((o) ^ (((o) >> 3) & 0x70))

// ===========================================================================
// Fused LayerNorm (q + kv in one launch). 32 positions per block so global
// loads are full 128B lines (float4). Padded [512][33] tile: conflict-free.
// Output (B*N, C) row-major, tf32-rounded.
// ===========================================================================
#define LN_SMEM (CC * 33 * 4)   // 67584 bytes

__global__ void __launch_bounds__(256) ln2_kernel(
    const float* __restrict__ qx, const float* __restrict__ kvx,
    const float* __restrict__ gq, const float* __restrict__ bq,
    const float* __restrict__ gkv, const float* __restrict__ bkv,
    float* __restrict__ oq, float* __restrict__ okv)
{
    extern __shared__ float tile[];          // [512][33]
    __shared__ float ps[8][33], pq[8][33];
    __shared__ float s_mu[32], s_rs[32];

    int bi = blockIdx.x;
    const float *x, *g, *bb;
    float* out;
    if (bi < MM / 32) { x = qx;  g = gq;  bb = bq;  out = oq; }
    else              { x = kvx; g = gkv; bb = bkv; out = okv; bi -= MM / 32; }

    int m0   = bi * 32;
    int bimg = m0 >> 12;
    int n0   = m0 & (NN - 1);
    const float* xb = x + (size_t)bimg * CC * NN + n0;
    int tid = threadIdx.x;

    #pragma unroll
    for (int u = 0; u < 16; u++) {
        int f = tid + u * 256;
        int c = f >> 3, qd = f & 7;
        float4 v = *(const float4*)(xb + (size_t)c * NN + qd * 4);
        tile[c * 33 + qd * 4 + 0] = v.x;
        tile[c * 33 + qd * 4 + 1] = v.y;
        tile[c * 33 + qd * 4 + 2] = v.z;
        tile[c * 33 + qd * 4 + 3] = v.w;
    }
    __syncthreads();

    {
        int p = tid & 31, w = tid >> 5;
        float sum = 0.f, sq = 0.f;
        #pragma unroll
        for (int i = 0; i < 64; i++) {
            float v = tile[(w + 8 * i) * 33 + p];
            sum += v; sq += v * v;
        }
        ps[w][p] = sum; pq[w][p] = sq;
    }
    __syncthreads();
    if (tid < 32) {
        float s = 0.f, s2 = 0.f;
        #pragma unroll
        for (int j = 0; j < 8; j++) { s += ps[j][tid]; s2 += pq[j][tid]; }
        float mu  = s * (1.f / 512.f);
        float var = s2 * (1.f / 512.f) - mu * mu;
        s_mu[tid] = mu;
        s_rs[tid] = rsqrtf(var + EPSV);
    }
    __syncthreads();

    #pragma unroll
    for (int u = 0; u < 16; u++) {
        int f  = tid + u * 256;
        int pp = f >> 7, c4 = (f & 127) * 4;
        float mu = s_mu[pp], rs = s_rs[pp];
        float4 v;
        v.x = round_tf32((tile[(c4 + 0) * 33 + pp] - mu) * rs * g[c4 + 0] + bb[c4 + 0]);
        v.y = round_tf32((tile[(c4 + 1) * 33 + pp] - mu) * rs * g[c4 + 1] + bb[c4 + 1]);
        v.z = round_tf32((tile[(c4 + 2) * 33 + pp] - mu) * rs * g[c4 + 2] + bb[c4 + 2]);
        v.w = round_tf32((tile[(c4 + 3) * 33 + pp] - mu) * rs * g[c4 + 3] + bb[c4 + 3]);
        *(float4*)(out + (size_t)(m0 + pp) * CC + c4) = v;
    }
}

// ===========================================================================
// prep: weight rounding (4*CC*CC) + RoPE table (NN*32) fused in one launch
// ===========================================================================
#define WELEMS (4 * CC * CC)
__global__ void __launch_bounds__(256) prep_kernel(
    const float* __restrict__ w0, const float* __restrict__ w1,
    const float* __restrict__ w2, const float* __restrict__ w3,
    float* __restrict__ dst, float* __restrict__ rope)
{
    int idx = blockIdx.x * 256 + threadIdx.x;
    if (idx < WELEMS) {
        int m = idx >> 18;
        int o = idx & (CC * CC - 1);
        const float* src = (m == 0) ? w0 : (m == 1) ? w1 : (m == 2) ? w2 : w3;
        dst[idx] = round_tf32(src[o]);
    } else if (idx < WELEMS + NN * 32) {
        int t = idx - WELEMS;
        int n = t >> 5, pp = t & 31;
        float inv = 1.f / powf(10000.f, (float)(2 * pp) / 64.f);
        float ang = (float)n * inv;
        rope[t * 2]     = sinf(ang);
        rope[t * 2 + 1] = cosf(ang);
    }
}

// ===========================================================================
// tf32 tensor-core GEMM core (FROZEN per R12: smem-crossbar-bound at 62%
// tensor util; 64x64 warp tiles are the best bytes/HMMA under 255 regs).
// CTA 128x128, 4 warps, BK=32, 3-stage cp.async, __launch_bounds__(128, 2)
// for TWO CTAs/SM (barrier-stall overlap between CTAs).
// ===========================================================================
#define BM 128
#define BN 128
#define BK 32
#define KITERS 16
#define STAGES 3
#define STAGE_A (BM * BK * 4)                  // 16384
#define STAGE_B (BN * BK * 4)                  // 16384
#define STAGE_BYTES (STAGE_A + STAGE_B)        // 32768
#define GEMM_SMEM (STAGES * STAGE_BYTES)       // 98304  (2 CTAs/SM)
#define TROW 132                               // transpose row stride (floats)

__device__ __forceinline__ void gemm_core(
    char* smem,
    const float* __restrict__ A, const float* __restrict__ Wm,
    const float* __restrict__ bias, float* __restrict__ Cout,
    const float* __restrict__ rope, const float* __restrict__ resid,
    int mode, int m0, int n0)
{
    uint32_t sbase = smem_u32(smem);
    int tid  = threadIdx.x;
    int wid  = tid >> 5, lane = tid & 31;
    int wm   = wid & 1,  wn   = wid >> 1;      // 2 x 2 warp grid, 64x64 tiles

    const float* Arow = A  + (size_t)m0 * 512;
    const float* Brow = Wm + (size_t)n0 * 512;

    auto load_stage = [&](int kt, int slot) {
        uint32_t st = sbase + slot * STAGE_BYTES;
        int k0 = kt * BK;
        #pragma unroll
        for (int u = 0; u < 8; u++) {
            int f = tid + u * 128;
            int r = f >> 3, q = f & 7;
            CP_ASYNC16(st + SWZ((uint32_t)(r * 128 + q * 16)),
                       Arow + (size_t)r * 512 + k0 + q * 4);
        }
        #pragma unroll
        for (int u = 0; u < 8; u++) {
            int f = tid + u * 128;
            int r = f >> 3, q = f & 7;
            CP_ASYNC16(st + STAGE_A + SWZ((uint32_t)(r * 128 + q * 16)),
                       Brow + (size_t)r * 512 + k0 + q * 4);
        }
        CP_COMMIT();
    };

    float acc[4][8][4];
    #pragma unroll
    for (int mt = 0; mt < 4; mt++)
        #pragma unroll
        for (int nt = 0; nt < 8; nt++)
            #pragma unroll
            for (int j = 0; j < 4; j++) acc[mt][nt][j] = 0.f;

    int a_row  = wm * 64 + (lane & 15);
    int a_kb   = (lane >> 4) << 4;
    int b_row  = wn * 64 + (lane & 7) + ((lane >> 4) & 1) * 8;
    int b_kb   = ((lane >> 3) & 1) << 4;

    load_stage(0, 0);
    load_stage(1, 1);

    uint32_t af[2][4][4], bf[2][4][4];

    for (int kt = 0; kt < KITERS; kt++) {
        int slot = kt - (kt / 3) * 3;
        if (kt < 15) asm volatile("cp.async.wait_group 1;" ::: "memory");
        else         asm volatile("cp.async.wait_group 0;" ::: "memory");
        __syncthreads();

        uint32_t sA = sbase + slot * STAGE_BYTES;
        uint32_t sB = sA + STAGE_A;

        #pragma unroll
        for (int mt = 0; mt < 4; mt++) {
            uint32_t ad = sA + SWZ((uint32_t)((a_row + mt * 16) * 128 + a_kb));
            LDMX4(af[0][mt][0], af[0][mt][1], af[0][mt][2], af[0][mt][3], ad);
        }
        #pragma unroll
        for (int np = 0; np < 4; np++) {
            uint32_t bd = sB + SWZ((uint32_t)((b_row + np * 16) * 128 + b_kb));
            LDMX4(bf[0][np][0], bf[0][np][1], bf[0][np][2], bf[0][np][3], bd);
        }

        #pragma unroll
        for (int ks = 0; ks < 4; ks++) {
            int cur = ks & 1, nxt = cur ^ 1;
            if (ks < 3) {
                #pragma unroll
                for (int mt = 0; mt < 4; mt++) {
                    uint32_t ad = sA + SWZ((uint32_t)((a_row + mt * 16) * 128 + (ks + 1) * 32 + a_kb));
                    LDMX4(af[nxt][mt][0], af[nxt][mt][1], af[nxt][mt][2], af[nxt][mt][3], ad);
                }
                #pragma unroll
                for (int np = 0; np < 4; np++) {
                    uint32_t bd = sB + SWZ((uint32_t)((b_row + np * 16) * 128 + (ks + 1) * 32 + b_kb));
                    LDMX4(bf[nxt][np][0], bf[nxt][np][1], bf[nxt][np][2], bf[nxt][np][3], bd);
                }
            }
            #pragma unroll
            for (int mt = 0; mt < 4; mt++)
                #pragma unroll
                for (int np = 0; np < 4; np++) {
                    MMA_TF32(acc[mt][2 * np],     af[cur][mt], bf[cur][np][0], bf[cur][np][1]);
                    MMA_TF32(acc[mt][2 * np + 1], af[cur][mt], bf[cur][np][2], bf[cur][np][3]);
                }
        }

        if (kt <= 13) {
            int kn = kt + 2;
            load_stage(kn, kn - (kn / 3) * 3);
        }
    }

    // ---------------- epilogue ----------------
    int rbase = m0 + wm * 64 + (lane >> 2);
    int cbase = n0 + wn * 64 + 2 * (lane & 3);

    if (mode == MODE_OUT) {
        float* tsm = (float*)smem;                   // [128][TROW]
        int bimg  = m0 >> 12;
        int nbase = m0 & (NN - 1);
        __syncthreads();
        #pragma unroll
        for (int mt = 0; mt < 4; mt++)
            #pragma unroll
            for (int half = 0; half < 2; half++) {
                int r    = rbase + mt * 16 + half * 8;
                int mloc = r - m0;
                const float* rr = resid + (size_t)r * 512;
                #pragma unroll
                for (int nt = 0; nt < 8; nt++) {
                    int c  = cbase + nt * 8;
                    int cl = c - n0;
                    tsm[cl * TROW + mloc] =
                        acc[mt][nt][2 * half]     + bias[c]     + rr[c];
                    tsm[(cl + 1) * TROW + mloc] =
                        acc[mt][nt][2 * half + 1] + bias[c + 1] + rr[c + 1];
                }
            }
        __syncthreads();
        #pragma unroll
        for (int u = 0; u < 32; u++) {
            int f  = tid + u * 128;
            int cl = f >> 5, q = f & 31;
            int cg = n0 + cl;
            float4 v = *(const float4*)&tsm[cl * TROW + q * 4];
            *(float4*)(Cout + (size_t)bimg * CC * NN + (size_t)cg * NN + nbase + q * 4) = v;
        }
        return;
    }

    #pragma unroll
    for (int mt = 0; mt < 4; mt++) {
        int r0 = rbase + mt * 16;
        #pragma unroll
        for (int half = 0; half < 2; half++) {
            int r    = r0 + half * 8;
            int npos = r & (NN - 1);
            const float* rp = rope + (size_t)npos * 64;
            #pragma unroll
            for (int nt = 0; nt < 8; nt++) {
                int   c  = cbase + nt * 8;
                float v0 = acc[mt][nt][2 * half]     + bias[c];
                float v1 = acc[mt][nt][2 * half + 1] + bias[c + 1];

                if (mode == MODE_ROPE) {
                    int   p = (c & 63) >> 1;
                    float s = rp[2 * p], co = rp[2 * p + 1];
                    float x0 = v0, x1 = v1;
                    v0 = x0 * co - x1 * s;
                    v1 = x0 * s  + x1 * co;
                }
                float* op = Cout + (size_t)r * 512 + c;
                op[0] = v0; op[1] = v1;
            }
        }
    }
}

// Fused Q/K/V projection: blockIdx.z selects operand set
__global__ void __launch_bounds__(128, 2) gemm_qkv(
    const float* __restrict__ qln, const float* __restrict__ kvln,
    const float* __restrict__ Wr,
    const float* __restrict__ bq, const float* __restrict__ bk,
    const float* __restrict__ bv,
    float* __restrict__ Qb, float* __restrict__ Kb, float* __restrict__ Vb,
    const float* __restrict__ rope)
{
    extern __shared__ char smem[];
    int z = blockIdx.z;
    const float* A    = (z == 0) ? qln : kvln;
    const float* Wm   = Wr + (size_t)z * CC * CC;
    const float* bias = (z == 0) ? bq : (z == 1) ? bk : bv;
    float*       Cout = (z == 0) ? Qb : (z == 1) ? Kb : Vb;
    int mode = (z == 2) ? MODE_PLAIN : MODE_ROPE;
    gemm_core(smem, A, Wm, bias, Cout, rope, nullptr, mode,
              blockIdx.y * BM, blockIdx.x * BN);
}

// O projection (+residual, NCHW-transposed output)
__global__ void __launch_bounds__(128, 2) gemm_out(
    const float* __restrict__ A, const float* __restrict__ Wm,
    const float* __restrict__ bias, float* __restrict__ Cout,
    const float* __restrict__ resid)
{
    extern __shared__ char smem[];
    gemm_core(smem, A, Wm, bias, Cout, nullptr, resid, MODE_OUT,
              blockIdx.y * BM, blockIdx.x * BN);
}

// ===========================================================================
// Window attention: one block per (head, window). Ws=64, D=64.
// __expf in softmax (MUFU path; error negligible vs tf32 rounding noise).
// ===========================================================================
#define ATTN_SMEM (4 * 64 * 68 * 4)

__global__ void __launch_bounds__(256) attn_kernel(
    const float* __restrict__ Q, const float* __restrict__ K,
    const float* __restrict__ V, const float* __restrict__ bt,
    float* __restrict__ O)
{
    extern __shared__ float sm[];
    float* Qs = sm;
    float* Kt = sm + 64 * 68;
    float* Vs = sm + 2 * 64 * 68;
    float* S  = sm + 3 * 64 * 68;
    __shared__ float tb[232];

    int bi  = blockIdx.x;
    int h   = bi >> 9;
    int rem = bi & 511;
    int b   = rem >> 6;
    int hn  = (rem >> 3) & 7;
    int wn  = rem & 7;
    int tid = threadIdx.x;

    for (int t = tid; t < 225; t += 256) tb[t] = bt[t * NHH + h];

    size_t base = ((size_t)b * NN) * CC + (size_t)h * DDIM;

    for (int f = tid; f < 1024; f += 256) {
        int s  = f >> 4, dq = f & 15;
        int wh = s >> 3, ww = s & 7;
        int n  = (hn * 8 + wh) * 64 + wn * 8 + ww;
        size_t ga = base + (size_t)n * CC + dq * 4;
        float4 qv = *(const float4*)(Q + ga);
        *(float4*)&Qs[s * 68 + dq * 4] = qv;
        float4 kv = *(const float4*)(K + ga);
        Kt[(dq * 4 + 0) * 68 + s] = kv.x;
        Kt[(dq * 4 + 1) * 68 + s] = kv.y;
        Kt[(dq * 4 + 2) * 68 + s] = kv.z;
        Kt[(dq * 4 + 3) * 68 + s] = kv.w;
        float4 vv = *(const float4*)(V + ga);
        *(float4*)&Vs[s * 68 + dq * 4] = vv;
    }
    __syncthreads();

    int tc = tid & 15, tr = tid >> 4;
    int r0 = tr * 4, c0 = tc * 4;

    float acc[4][4] = {};
    for (int d = 0; d < 64; d += 4) {
        float4 kf[4];
        #pragma unroll
        for (int u = 0; u < 4; u++) kf[u] = *(const float4*)&Kt[(d + u) * 68 + c0];
        #pragma unroll
        for (int ii = 0; ii < 4; ii++) {
            float4 qf = *(const float4*)&Qs[(r0 + ii) * 68 + d];
            acc[ii][0] += qf.x*kf[0].x + qf.y*kf[1].x + qf.z*kf[2].x + qf.w*kf[3].x;
            acc[ii][1] += qf.x*kf[0].y + qf.y*kf[1].y + qf.z*kf[2].y + qf.w*kf[3].y;
            acc[ii][2] += qf.x*kf[0].z + qf.y*kf[1].z + qf.z*kf[2].z + qf.w*kf[3].z;
            acc[ii][3] += qf.x*kf[0].w + qf.y*kf[1].w + qf.z*kf[2].w + qf.w*kf[3].w;
        }
    }

    #pragma unroll
    for (int ii = 0; ii < 4; ii++) {
        int i = r0 + ii; int ih = i >> 3, iw = i & 7;
        #pragma unroll
        for (int jj = 0; jj < 4; jj++) {
            int j = c0 + jj; int jh = j >> 3, jw = j & 7;
            int ridx = (ih - jh + 7) * 15 + (iw - jw + 7);
            S[i * 68 + j] = acc[ii][jj] * SCALEV + tb[ridx];
        }
    }
    __syncthreads();

    {
        int r = tid >> 2, qg = tid & 3;
        float* row = S + r * 68 + qg * 16;
        float mx = -INFINITY;
        #pragma unroll
        for (int j = 0; j < 16; j++) mx = fmaxf(mx, row[j]);
        mx = fmaxf(mx, __shfl_xor_sync(0xffffffffu, mx, 1));
        mx = fmaxf(mx, __shfl_xor_sync(0xffffffffu, mx, 2));
        float e[16], sum = 0.f;
        #pragma unroll
        for (int j = 0; j < 16; j++) { e[j] = __expf(row[j] - mx); sum += e[j]; }
        sum += __shfl_xor_sync(0xffffffffu, sum, 1);
        sum += __shfl_xor_sync(0xffffffffu, sum, 2);
        float inv = 1.f / sum;
        #pragma unroll
        for (int j = 0; j < 16; j++) row[j] = e[j] * inv;
    }
    __syncthreads();

    float oacc[4][4] = {};
    for (int j = 0; j < 64; j += 4) {
        float4 vf[4];
        #pragma unroll
        for (int u = 0; u < 4; u++) vf[u] = *(const float4*)&Vs[(j + u) * 68 + c0];
        #pragma unroll
        for (int ii = 0; ii < 4; ii++) {
            float4 pf = *(const float4*)&S[(r0 + ii) * 68 + j];
            oacc[ii][0] += pf.x*vf[0].x + pf.y*vf[1].x + pf.z*vf[2].x + pf.w*vf[3].x;
            oacc[ii][1] += pf.x*vf[0].y + pf.y*vf[1].y + pf.z*vf[2].y + pf.w*vf[3].y;
            oacc[ii][2] += pf.x*vf[0].z + pf.y*vf[1].z + pf.z*vf[2].z + pf.w*vf[3].z;
            oacc[ii][3] += pf.x*vf[0].w + pf.y*vf[1].w + pf.z*vf[2].w + pf.w*vf[3].w;
        }
    }

    #pragma unroll
    for (int ii = 0; ii < 4; ii++) {
        int s  = r0 + ii;
        int wh = s >> 3, ww = s & 7;
        int n  = (hn * 8 + wh) * 64 + wn * 8 + ww;
        *(float4*)(O + base + (size_t)n * CC + c0) =
            make_float4(round_tf32(oacc[ii][0]), round_tf32(oacc[ii][1]),
                        round_tf32(oacc[ii][2]), round_tf32(oacc[ii][3]));
    }
}

// ===========================================================================
extern "C" void kernel_launch(void* const* d_in, const int* in_sizes, int n_in,
                              void* d_out, int out_size)
{
    const float* q    = (const float*)d_in[0];
    const float* kv   = (const float*)d_in[1];
    const float* g_q  = (const float*)d_in[2];
    const float* b_q  = (const float*)d_in[3];
    const float* g_kv = (const float*)d_in[4];
    const float* b_kv = (const float*)d_in[5];
    const float* Wq   = (const float*)d_in[6];
    const float* bq   = (const float*)d_in[7];
    const float* Wk   = (const float*)d_in[8];
    const float* bk   = (const float*)d_in[9];
    const float* Wv   = (const float*)d_in[10];
    const float* bv   = (const float*)d_in[11];
    const float* Wo   = (const float*)d_in[12];
    const float* bo   = (const float*)d_in[13];
    const float* bt   = (const float*)d_in[14];
    float* out = (float*)d_out;

    void *p_big, *p_rope, *p_Wr;
    cudaGetSymbolAddress(&p_big,  g_big);
    cudaGetSymbolAddress(&p_rope, g_rope);
    cudaGetSymbolAddress(&p_Wr,   g_Wr);

    float* qln  = (float*)p_big + 0 * (size_t)MM * CC;
    float* kvln = (float*)p_big + 1 * (size_t)MM * CC;
    float* Qb   = (float*)p_big + 2 * (size_t)MM * CC;
    float* Kb   = (float*)p_big + 3 * (size_t)MM * CC;
    float* Vb   = (float*)p_big + 4 * (size_t)MM * CC;
    float* AO   = kvln;                 // aliased: kvln dead after V GEMM
    float* Wr   = (float*)p_Wr;
    float* rope = (float*)p_rope;

    cudaFuncSetAttribute(attn_kernel, cudaFuncAttributeMaxDynamicSharedMemorySize, ATTN_SMEM);
    cudaFuncSetAttribute(ln2_kernel,  cudaFuncAttributeMaxDynamicSharedMemorySize, LN_SMEM);
    cudaFuncSetAttribute(gemm_qkv,    cudaFuncAttributeMaxDynamicSharedMemorySize, GEMM_SMEM);
    cudaFuncSetAttribute(gemm_out,    cudaFuncAttributeMaxDynamicSharedMemorySize, GEMM_SMEM);

    // launch order: attn sits at captured ncu index 3 this round
    ln2_kernel<<<2 * (MM / 32), 256, LN_SMEM>>>(q, kv, g_q, b_q, g_kv, b_kv,
                                                qln, kvln);           // 0
    prep_kernel<<<(WELEMS + NN * 32 + 255) / 256, 256>>>(Wq, Wk, Wv, Wo, Wr, rope); // 1

    dim3 g_qkv(4, 256, 3);
    gemm_qkv<<<g_qkv, 128, GEMM_SMEM>>>(qln, kvln, Wr, bq, bk, bv,
                                        Qb, Kb, Vb, rope);            // 2

    attn_kernel<<<NHH * BB * 64, 256, ATTN_SMEM>>>(Qb, Kb, Vb, bt, AO); // 3 <- profiled

    dim3 g_o(4, 256);
    gemm_out<<<g_o, 128, GEMM_SMEM>>>(AO, Wr + 3 * (size_t)CC * CC, bo, out, qln);
}

// round 14
// speedup vs baseline: 1.3152x; 1.0722x over previous
#include <cuda_runtime.h>
#include <math.h>
#include <stdint.h>

// Problem constants
#define BB   8
#define CC   512
#define NN   4096            // H*W
#define MM   (BB*NN)         // 32768 tokens
#define NHH  8
#define DDIM 64
#define EPSV 1e-5f
#define SCALEV 0.125f        // 64^-0.5

#define MODE_PLAIN 0
#define MODE_ROPE  1
#define MODE_OUT   2

// Scratch (device globals; container memory is tight: 5 big buffers, AO aliases kvln)
__device__ float g_big [5][MM*CC];  // 0:qln 1:kvln/AO 2:Q 3:K 4:V
__device__ float g_rope[NN*32*2];   // [n][p][{sin,cos}]
__device__ float g_Wr  [4][CC*CC];  // tf32-rounded weights

// ===========================================================================
// helpers
// ===========================================================================
__device__ __forceinline__ uint32_t smem_u32(const void* p) {
    uint32_t a;
    asm("{ .reg .u64 t; cvta.to.shared.u64 t, %1; cvt.u32.u64 %0, t; }" : "=r"(a) : "l"(p));
    return a;
}
__device__ __forceinline__ float round_tf32(float x) {
    uint32_t r;
    asm("cvt.rna.tf32.f32 %0, %1;" : "=r"(r) : "f"(x));
    return __uint_as_float(r);
}
#define CP_ASYNC16(dst, src) \
    asm volatile("cp.async.cg.shared.global [%0], [%1], 16;" :: "r"(dst), "l"(src))
#define CP_COMMIT() asm volatile("cp.async.commit_group;" ::: "memory")

#define LDMX4(r0, r1, r2, r3, addr) \
    asm volatile("ldmatrix.sync.aligned.m8n8.x4.shared.b16 {%0,%1,%2,%3}, [%4];" \
        : "=r"(r0), "=r"(r1), "=r"(r2), "=r"(r3) : "r"(addr))

#define MMA_TF32(d, a, b0v, b1v) \
    asm volatile("mma.sync.aligned.m16n8k8.row.col.f32.tf32.tf32.f32 " \
        "{%0,%1,%2,%3}, {%4,%5,%6,%7}, {%8,%9}, {%0,%1,%2,%3};" \
        : "+f"((d)[0]), "+f"((d)[1]), "+f"((d)[2]), "+f"((d)[3]) \
        : "r"((a)[0]), "r"((a)[1]), "r"((a)[2]), "r"((a)[3]), "r"(b0v), "r"(b1v))

// SW128 swizzle on a byte offset relative to a 1024B-aligned tile base
#define SWZ(o) ((o) ^ (((o) >> 3) & 0x70))

// ===========================================================================
// Fused LayerNorm (q + kv). 32 positions/block, full-line float4 loads,
// padded [512][33] tile. Output (B*N, C) row-major, tf32-rounded.
// ===========================================================================
#define LN_SMEM (CC * 33 * 4)   // 67584 bytes

__global__ void __launch_bounds__(256) ln2_kernel(
    const float* __restrict__ qx, const float* __restrict__ kvx,
    const float* __restrict__ gq, const float* __restrict__ bq,
    const float* __restrict__ gkv, const float* __restrict__ bkv,
    float* __restrict__ oq, float* __restrict__ okv)
{
    extern __shared__ float tile[];          // [512][33]
    __shared__ float ps[8][33], pq[8][33];
    __shared__ float s_mu[32], s_rs[32];

    int bi = blockIdx.x;
    const float *x, *g, *bb;
    float* out;
    if (bi < MM / 32) { x = qx;  g = gq;  bb = bq;  out = oq; }
    else              { x = kvx; g = gkv; bb = bkv; out = okv; bi -= MM / 32; }

    int m0   = bi * 32;
    int bimg = m0 >> 12;
    int n0   = m0 & (NN - 1);
    const float* xb = x + (size_t)bimg * CC * NN + n0;
    int tid = threadIdx.x;

    #pragma unroll
    for (int u = 0; u < 16; u++) {
        int f = tid + u * 256;
        int c = f >> 3, qd = f & 7;
        float4 v = *(const float4*)(xb + (size_t)c * NN + qd * 4);
        tile[c * 33 + qd * 4 + 0] = v.x;
        tile[c * 33 + qd * 4 + 1] = v.y;
        tile[c * 33 + qd * 4 + 2] = v.z;
        tile[c * 33 + qd * 4 + 3] = v.w;
    }
    __syncthreads();

    {
        int p = tid & 31, w = tid >> 5;
        float sum = 0.f, sq = 0.f;
        #pragma unroll
        for (int i = 0; i < 64; i++) {
            float v = tile[(w + 8 * i) * 33 + p];
            sum += v; sq += v * v;
        }
        ps[w][p] = sum; pq[w][p] = sq;
    }
    __syncthreads();
    if (tid < 32) {
        float s = 0.f, s2 = 0.f;
        #pragma unroll
        for (int j = 0; j < 8; j++) { s += ps[j][tid]; s2 += pq[j][tid]; }
        float mu  = s * (1.f / 512.f);
        float var = s2 * (1.f / 512.f) - mu * mu;
        s_mu[tid] = mu;
        s_rs[tid] = rsqrtf(var + EPSV);
    }
    __syncthreads();

    #pragma unroll
    for (int u = 0; u < 16; u++) {
        int f  = tid + u * 256;
        int pp = f >> 7, c4 = (f & 127) * 4;
        float mu = s_mu[pp], rs = s_rs[pp];
        float4 v;
        v.x = round_tf32((tile[(c4 + 0) * 33 + pp] - mu) * rs * g[c4 + 0] + bb[c4 + 0]);
        v.y = round_tf32((tile[(c4 + 1) * 33 + pp] - mu) * rs * g[c4 + 1] + bb[c4 + 1]);
        v.z = round_tf32((tile[(c4 + 2) * 33 + pp] - mu) * rs * g[c4 + 2] + bb[c4 + 2]);
        v.w = round_tf32((tile[(c4 + 3) * 33 + pp] - mu) * rs * g[c4 + 3] + bb[c4 + 3]);
        *(float4*)(out + (size_t)(m0 + pp) * CC + c4) = v;
    }
}

// ===========================================================================
// prep: weight rounding + RoPE table
// ===========================================================================
#define WELEMS (4 * CC * CC)
__global__ void __launch_bounds__(256) prep_kernel(
    const float* __restrict__ w0, const float* __restrict__ w1,
    const float* __restrict__ w2, const float* __restrict__ w3,
    float* __restrict__ dst, float* __restrict__ rope)
{
    int idx = blockIdx.x * 256 + threadIdx.x;
    if (idx < WELEMS) {
        int m = idx >> 18;
        int o = idx & (CC * CC - 1);
        const float* src = (m == 0) ? w0 : (m == 1) ? w1 : (m == 2) ? w2 : w3;
        dst[idx] = round_tf32(src[o]);
    } else if (idx < WELEMS + NN * 32) {
        int t = idx - WELEMS;
        int n = t >> 5, pp = t & 31;
        float inv = 1.f / powf(10000.f, (float)(2 * pp) / 64.f);
        float ang = (float)n * inv;
        rope[t * 2]     = sinf(ang);
        rope[t * 2 + 1] = cosf(ang);
    }
}

// ===========================================================================
// tf32 tensor-core GEMM core (FROZEN: smem-crossbar-bound at 62% tensor).
// CTA 128x128, 4 warps of 64x64, BK=32, 3-stage cp.async, (128, 2).
// Q/K/V outputs are tf32-rounded (rna) since attention now consumes them
// through mma.sync (unbiased operands).
// ===========================================================================
#define BM 128
#define BN 128
#define BK 32
#define KITERS 16
#define STAGES 3
#define STAGE_A (BM * BK * 4)                  // 16384
#define STAGE_B (BN * BK * 4)                  // 16384
#define STAGE_BYTES (STAGE_A + STAGE_B)        // 32768
#define GEMM_SMEM (STAGES * STAGE_BYTES)       // 98304  (2 CTAs/SM)
#define TROW 132

__device__ __forceinline__ void gemm_core(
    char* smem,
    const float* __restrict__ A, const float* __restrict__ Wm,
    const float* __restrict__ bias, float* __restrict__ Cout,
    const float* __restrict__ rope, const float* __restrict__ resid,
    int mode, int m0, int n0)
{
    uint32_t sbase = smem_u32(smem);
    int tid  = threadIdx.x;
    int wid  = tid >> 5, lane = tid & 31;
    int wm   = wid & 1,  wn   = wid >> 1;

    const float* Arow = A  + (size_t)m0 * 512;
    const float* Brow = Wm + (size_t)n0 * 512;

    auto load_stage = [&](int kt, int slot) {
        uint32_t st = sbase + slot * STAGE_BYTES;
        int k0 = kt * BK;
        #pragma unroll
        for (int u = 0; u < 8; u++) {
            int f = tid + u * 128;
            int r = f >> 3, q = f & 7;
            CP_ASYNC16(st + SWZ((uint32_t)(r * 128 + q * 16)),
                       Arow + (size_t)r * 512 + k0 + q * 4);
        }
        #pragma unroll
        for (int u = 0; u < 8; u++) {
            int f = tid + u * 128;
            int r = f >> 3, q = f & 7;
            CP_ASYNC16(st + STAGE_A + SWZ((uint32_t)(r * 128 + q * 16)),
                       Brow + (size_t)r * 512 + k0 + q * 4);
        }
        CP_COMMIT();
    };

    float acc[4][8][4];
    #pragma unroll
    for (int mt = 0; mt < 4; mt++)
        #pragma unroll
        for (int nt = 0; nt < 8; nt++)
            #pragma unroll
            for (int j = 0; j < 4; j++) acc[mt][nt][j] = 0.f;

    int a_row  = wm * 64 + (lane & 15);
    int a_kb   = (lane >> 4) << 4;
    int b_row  = wn * 64 + (lane & 7) + ((lane >> 4) & 1) * 8;
    int b_kb   = ((lane >> 3) & 1) << 4;

    load_stage(0, 0);
    load_stage(1, 1);

    uint32_t af[2][4][4], bf[2][4][4];

    for (int kt = 0; kt < KITERS; kt++) {
        int slot = kt - (kt / 3) * 3;
        if (kt < 15) asm volatile("cp.async.wait_group 1;" ::: "memory");
        else         asm volatile("cp.async.wait_group 0;" ::: "memory");
        __syncthreads();

        uint32_t sA = sbase + slot * STAGE_BYTES;
        uint32_t sB = sA + STAGE_A;

        #pragma unroll
        for (int mt = 0; mt < 4; mt++) {
            uint32_t ad = sA + SWZ((uint32_t)((a_row + mt * 16) * 128 + a_kb));
            LDMX4(af[0][mt][0], af[0][mt][1], af[0][mt][2], af[0][mt][3], ad);
        }
        #pragma unroll
        for (int np = 0; np < 4; np++) {
            uint32_t bd = sB + SWZ((uint32_t)((b_row + np * 16) * 128 + b_kb));
            LDMX4(bf[0][np][0], bf[0][np][1], bf[0][np][2], bf[0][np][3], bd);
        }

        #pragma unroll
        for (int ks = 0; ks < 4; ks++) {
            int cur = ks & 1, nxt = cur ^ 1;
            if (ks < 3) {
                #pragma unroll
                for (int mt = 0; mt < 4; mt++) {
                    uint32_t ad = sA + SWZ((uint32_t)((a_row + mt * 16) * 128 + (ks + 1) * 32 + a_kb));
                    LDMX4(af[nxt][mt][0], af[nxt][mt][1], af[nxt][mt][2], af[nxt][mt][3], ad);
                }
                #pragma unroll
                for (int np = 0; np < 4; np++) {
                    uint32_t bd = sB + SWZ((uint32_t)((b_row + np * 16) * 128 + (ks + 1) * 32 + b_kb));
                    LDMX4(bf[nxt][np][0], bf[nxt][np][1], bf[nxt][np][2], bf[nxt][np][3], bd);
                }
            }
            #pragma unroll
            for (int mt = 0; mt < 4; mt++)
                #pragma unroll
                for (int np = 0; np < 4; np++) {
                    MMA_TF32(acc[mt][2 * np],     af[cur][mt], bf[cur][np][0], bf[cur][np][1]);
                    MMA_TF32(acc[mt][2 * np + 1], af[cur][mt], bf[cur][np][2], bf[cur][np][3]);
                }
        }

        if (kt <= 13) {
            int kn = kt + 2;
            load_stage(kn, kn - (kn / 3) * 3);
        }
    }

    // ---------------- epilogue ----------------
    int rbase = m0 + wm * 64 + (lane >> 2);
    int cbase = n0 + wn * 64 + 2 * (lane & 3);

    if (mode == MODE_OUT) {
        float* tsm = (float*)smem;                   // [128][TROW]
        int bimg  = m0 >> 12;
        int nbase = m0 & (NN - 1);
        __syncthreads();
        #pragma unroll
        for (int mt = 0; mt < 4; mt++)
            #pragma unroll
            for (int half = 0; half < 2; half++) {
                int r    = rbase + mt * 16 + half * 8;
                int mloc = r - m0;
                const float* rr = resid + (size_t)r * 512;
                #pragma unroll
                for (int nt = 0; nt < 8; nt++) {
                    int c  = cbase + nt * 8;
                    int cl = c - n0;
                    tsm[cl * TROW + mloc] =
                        acc[mt][nt][2 * half]     + bias[c]     + rr[c];
                    tsm[(cl + 1) * TROW + mloc] =
                        acc[mt][nt][2 * half + 1] + bias[c + 1] + rr[c + 1];
                }
            }
        __syncthreads();
        #pragma unroll
        for (int u = 0; u < 32; u++) {
            int f  = tid + u * 128;
            int cl = f >> 5, q = f & 31;
            int cg = n0 + cl;
            float4 v = *(const float4*)&tsm[cl * TROW + q * 4];
            *(float4*)(Cout + (size_t)bimg * CC * NN + (size_t)cg * NN + nbase + q * 4) = v;
        }
        return;
    }

    #pragma unroll
    for (int mt = 0; mt < 4; mt++) {
        int r0 = rbase + mt * 16;
        #pragma unroll
        for (int half = 0; half < 2; half++) {
            int r    = r0 + half * 8;
            int npos = r & (NN - 1);
            const float* rp = rope + (size_t)npos * 64;
            #pragma unroll
            for (int nt = 0; nt < 8; nt++) {
                int   c  = cbase + nt * 8;
                float v0 = acc[mt][nt][2 * half]     + bias[c];
                float v1 = acc[mt][nt][2 * half + 1] + bias[c + 1];

                if (mode == MODE_ROPE) {
                    int   p = (c & 63) >> 1;
                    float s = rp[2 * p], co = rp[2 * p + 1];
                    float x0 = v0, x1 = v1;
                    v0 = x0 * co - x1 * s;
                    v1 = x0 * s  + x1 * co;
                }
                float* op = Cout + (size_t)r * 512 + c;
                op[0] = round_tf32(v0);
                op[1] = round_tf32(v1);
            }
        }
    }
}

__global__ void __launch_bounds__(128, 2) gemm_qkv(
    const float* __restrict__ qln, const float* __restrict__ kvln,
    const float* __restrict__ Wr,
    const float* __restrict__ bq, const float* __restrict__ bk,
    const float* __restrict__ bv,
    float* __restrict__ Qb, float* __restrict__ Kb, float* __restrict__ Vb,
    const float* __restrict__ rope)
{
    extern __shared__ char smem[];
    int z = blockIdx.z;
    const float* A    = (z == 0) ? qln : kvln;
    const float* Wm   = Wr + (size_t)z * CC * CC;
    const float* bias = (z == 0) ? bq : (z == 1) ? bk : bv;
    float*       Cout = (z == 0) ? Qb : (z == 1) ? Kb : Vb;
    int mode = (z == 2) ? MODE_PLAIN : MODE_ROPE;
    gemm_core(smem, A, Wm, bias, Cout, rope, nullptr, mode,
              blockIdx.y * BM, blockIdx.x * BN);
}

__global__ void __launch_bounds__(128, 2) gemm_out(
    const float* __restrict__ A, const float* __restrict__ Wm,
    const float* __restrict__ bias, float* __restrict__ Cout,
    const float* __restrict__ resid)
{
    extern __shared__ char smem[];
    gemm_core(smem, A, Wm, bias, Cout, nullptr, resid, MODE_OUT,
              blockIdx.y * BM, blockIdx.x * BN);
}

// ===========================================================================
// Tensor-core window attention: one block per (head, window). Ws=64, D=64.
// 128 threads / 4 warps, 2x2 grid of 32x32 warp tiles, mma.sync tf32 for
// both S=Q K^T and O=P V. Q/K/P in SW128 two-chunk layouts; V transposed
// with 272B row stride (per-lane ldmatrix rows, conflict-free).
// ===========================================================================
#define AQ_OFF  0
#define AK_OFF  16384
#define AV_OFF  32768            // Vt: 64 rows x 272B = 17408
#define AP_OFF  50176
#define ATTN_SMEM (50176 + 16384)   // 66560
#define VROW 272

__global__ void __launch_bounds__(128, 3) attn_kernel(
    const float* __restrict__ Q, const float* __restrict__ K,
    const float* __restrict__ V, const float* __restrict__ bt,
    float* __restrict__ O)
{
    extern __shared__ char asm_[];
    uint32_t sb = smem_u32(asm_);
    __shared__ float tb[232];

    int bi  = blockIdx.x;
    int h   = bi >> 9;
    int rem = bi & 511;
    int b   = rem >> 6;
    int hn  = (rem >> 3) & 7;   // window row
    int wwi = rem & 7;          // window col
    int tid = threadIdx.x;
    int wid = tid >> 5, lane = tid & 31;
    int wm  = wid & 1, wn = wid >> 1;   // 2x2 warp grid

    for (int t = tid; t < 225; t += 128) tb[t] = bt[t * NHH + h];

    size_t base = ((size_t)b * NN) * CC + (size_t)h * DDIM;

    // ---- load Q, K (dq-fastest; swizzled 2-chunk layout) ----
    #pragma unroll
    for (int u = 0; u < 8; u++) {
        int f = tid + u * 128;
        int s = f >> 4, dq = f & 15;
        int th = s >> 3, tw = s & 7;
        int n  = (hn * 8 + th) * 64 + wwi * 8 + tw;
        size_t ga = base + (size_t)n * CC + dq * 4;
        uint32_t off = (uint32_t)((dq >> 3) * 8192 + SWZ(s * 128 + (dq & 7) * 16));
        *(float4*)(asm_ + AQ_OFF + off) = *(const float4*)(Q + ga);
        *(float4*)(asm_ + AK_OFF + off) = *(const float4*)(K + ga);
    }
    // ---- load V transposed (s-fastest to avoid store conflicts) ----
    #pragma unroll
    for (int u = 0; u < 8; u++) {
        int f = tid + u * 128;
        int s = f & 63, dq = f >> 6;
        int th = s >> 3, tw = s & 7;
        int n  = (hn * 8 + th) * 64 + wwi * 8 + tw;
        float4 v = *(const float4*)(V + base + (size_t)n * CC + dq * 4);
        float* vt = (float*)(asm_ + AV_OFF);
        vt[(dq * 4 + 0) * (VROW / 4) + s] = v.x;
        vt[(dq * 4 + 1) * (VROW / 4) + s] = v.y;
        vt[(dq * 4 + 2) * (VROW / 4) + s] = v.z;
        vt[(dq * 4 + 3) * (VROW / 4) + s] = v.w;
    }
    __syncthreads();

    // fragment address components (same intra-warp pattern as gemm_core)
    int a_row = wm * 32 + (lane & 15);               // + mt*16
    int a_kb  = (lane >> 4) << 4;
    int b_row = wn * 32 + (lane & 7) + ((lane >> 4) & 1) * 8;   // + np*16
    int b_kb  = ((lane >> 3) & 1) << 4;

    // ---- phase 1: S = Q K^T ----
    float acc[2][4][4];
    #pragma unroll
    for (int mt = 0; mt < 2; mt++)
        #pragma unroll
        for (int nt = 0; nt < 4; nt++)
            #pragma unroll
            for (int j = 0; j < 4; j++) acc[mt][nt][j] = 0.f;

    #pragma unroll
    for (int ks = 0; ks < 8; ks++) {
        uint32_t kc = (uint32_t)(ks >> 2) * 8192;
        uint32_t kb = (uint32_t)(ks & 3) * 32;
        uint32_t af[2][4], bf[2][4];
        #pragma unroll
        for (int mt = 0; mt < 2; mt++) {
            uint32_t ad = sb + AQ_OFF + kc + SWZ((uint32_t)((a_row + mt * 16) * 128 + kb + a_kb));
            LDMX4(af[mt][0], af[mt][1], af[mt][2], af[mt][3], ad);
        }
        #pragma unroll
        for (int np = 0; np < 2; np++) {
            uint32_t bd = sb + AK_OFF + kc + SWZ((uint32_t)((b_row + np * 16) * 128 + kb + b_kb));
            LDMX4(bf[np][0], bf[np][1], bf[np][2], bf[np][3], bd);
        }
        #pragma unroll
        for (int mt = 0; mt < 2; mt++)
            #pragma unroll
            for (int np = 0; np < 2; np++) {
                MMA_TF32(acc[mt][2 * np],     af[mt], bf[np][0], bf[np][1]);
                MMA_TF32(acc[mt][2 * np + 1], af[mt], bf[np][2], bf[np][3]);
            }
    }

    // ---- scale + rel-pos bias -> P buffer (Q-style layout) ----
    {
        float* pbuf = (float*)(asm_ + AP_OFF);
        int rb = wm * 32 + (lane >> 2);
        int cb = wn * 32 + 2 * (lane & 3);
        #pragma unroll
        for (int mt = 0; mt < 2; mt++)
            #pragma unroll
            for (int half = 0; half < 2; half++) {
                int r  = rb + mt * 16 + half * 8;
                int ih = r >> 3, iw = r & 7;
                #pragma unroll
                for (int nt = 0; nt < 4; nt++) {
                    int c = cb + nt * 8;
                    uint32_t off = (uint32_t)((c >> 5) * 8192 + SWZ(r * 128 + (c & 31) * 4));
                    float* dst = (float*)((char*)pbuf + off);
                    int j0h = c >> 3, j0w = c & 7;
                    int j1h = (c + 1) >> 3, j1w = (c + 1) & 7;
                    dst[0] = acc[mt][nt][2 * half]     * SCALEV + tb[(ih - j0h + 7) * 15 + (iw - j0w + 7)];
                    dst[1] = acc[mt][nt][2 * half + 1] * SCALEV + tb[(ih - j1h + 7) * 15 + (iw - j1w + 7)];
                }
            }
    }
    __syncthreads();

    // ---- softmax on P (64 rows x 2 lanes, 32 cols each) ----
    {
        float* pbuf = (float*)(asm_ + AP_OFF);
        int r = tid >> 1, cg = tid & 1;
        char* rowb = (char*)pbuf + cg * 8192;
        float v[32];
        #pragma unroll
        for (int j = 0; j < 32; j++)
            v[j] = *(float*)(rowb + SWZ((uint32_t)(r * 128 + j * 4)));
        float mx = v[0];
        #pragma unroll
        for (int j = 1; j < 32; j++) mx = fmaxf(mx, v[j]);
        mx = fmaxf(mx, __shfl_xor_sync(0xffffffffu, mx, 1));
        float sum = 0.f;
        #pragma unroll
        for (int j = 0; j < 32; j++) { v[j] = __expf(v[j] - mx); sum += v[j]; }
        sum += __shfl_xor_sync(0xffffffffu, sum, 1);
        float inv = 1.f / sum;
        #pragma unroll
        for (int j = 0; j < 32; j++)
            *(float*)(rowb + SWZ((uint32_t)(r * 128 + j * 4))) = round_tf32(v[j] * inv);
    }
    __syncthreads();

    // ---- phase 2: O = P V  (A = P, B = Vt rows=d, k=token) ----
    float oacc[2][4][4];
    #pragma unroll
    for (int mt = 0; mt < 2; mt++)
        #pragma unroll
        for (int nt = 0; nt < 4; nt++)
            #pragma unroll
            for (int j = 0; j < 4; j++) oacc[mt][nt][j] = 0.f;

    #pragma unroll
    for (int ks = 0; ks < 8; ks++) {
        uint32_t kc = (uint32_t)(ks >> 2) * 8192;
        uint32_t kb = (uint32_t)(ks & 3) * 32;
        uint32_t af[2][4], bf[2][4];
        #pragma unroll
        for (int mt = 0; mt < 2; mt++) {
            uint32_t ad = sb + AP_OFF + kc + SWZ((uint32_t)((a_row + mt * 16) * 128 + kb + a_kb));
            LDMX4(af[mt][0], af[mt][1], af[mt][2], af[mt][3], ad);
        }
        #pragma unroll
        for (int np = 0; np < 2; np++) {
            uint32_t bd = sb + AV_OFF
                        + (uint32_t)(b_row + np * 16) * VROW
                        + (uint32_t)(ks * 32) + (uint32_t)b_kb;
            LDMX4(bf[np][0], bf[np][1], bf[np][2], bf[np][3], bd);
        }
        #pragma unroll
        for (int mt = 0; mt < 2; mt++)
            #pragma unroll
            for (int np = 0; np < 2; np++) {
                MMA_TF32(oacc[mt][2 * np],     af[mt], bf[np][0], bf[np][1]);
                MMA_TF32(oacc[mt][2 * np + 1], af[mt], bf[np][2], bf[np][3]);
            }
    }

    // ---- store O (tf32-rounded; feeds O-projection GEMM) ----
    {
        int rb = wm * 32 + (lane >> 2);
        int cb = wn * 32 + 2 * (lane & 3);
        #pragma unroll
        for (int mt = 0; mt < 2; mt++)
            #pragma unroll
            for (int half = 0; half < 2; half++) {
                int s  = rb + mt * 16 + half * 8;
                int th = s >> 3, tw = s & 7;
                int n  = (hn * 8 + th) * 64 + wwi * 8 + tw;
                float* op = O + base + (size_t)n * CC;
                #pragma unroll
                for (int nt = 0; nt < 4; nt++) {
                    int c = cb + nt * 8;
                    op[c]     = round_tf32(oacc[mt][nt][2 * half]);
                    op[c + 1] = round_tf32(oacc[mt][nt][2 * half + 1]);
                }
            }
    }
}

// ===========================================================================
extern "C" void kernel_launch(void* const* d_in, const int* in_sizes, int n_in,
                              void* d_out, int out_size)
{
    const float* q    = (const float*)d_in[0];
    const float* kv   = (const float*)d_in[1];
    const float* g_q  = (const float*)d_in[2];
    const float* b_q  = (const float*)d_in[3];
    const float* g_kv = (const float*)d_in[4];
    const float* b_kv = (const float*)d_in[5];
    const float* Wq   = (const float*)d_in[6];
    const float* bq   = (const float*)d_in[7];
    const float* Wk   = (const float*)d_in[8];
    const float* bk   = (const float*)d_in[9];
    const float* Wv   = (const float*)d_in[10];
    const float* bv   = (const float*)d_in[11];
    const float* Wo   = (const float*)d_in[12];
    const float* bo   = (const float*)d_in[13];
    const float* bt   = (const float*)d_in[14];
    float* out = (float*)d_out;

    void *p_big, *p_rope, *p_Wr;
    cudaGetSymbolAddress(&p_big,  g_big);
    cudaGetSymbolAddress(&p_rope, g_rope);
    cudaGetSymbolAddress(&p_Wr,   g_Wr);

    float* qln  = (float*)p_big + 0 * (size_t)MM * CC;
    float* kvln = (float*)p_big + 1 * (size_t)MM * CC;
    float* Qb   = (float*)p_big + 2 * (size_t)MM * CC;
    float* Kb   = (float*)p_big + 3 * (size_t)MM * CC;
    float* Vb   = (float*)p_big + 4 * (size_t)MM * CC;
    float* AO   = kvln;                 // aliased: kvln dead after V GEMM
    float* Wr   = (float*)p_Wr;
    float* rope = (float*)p_rope;

    cudaFuncSetAttribute(attn_kernel, cudaFuncAttributeMaxDynamicSharedMemorySize, ATTN_SMEM);
    cudaFuncSetAttribute(ln2_kernel,  cudaFuncAttributeMaxDynamicSharedMemorySize, LN_SMEM);
    cudaFuncSetAttribute(gemm_qkv,    cudaFuncAttributeMaxDynamicSharedMemorySize, GEMM_SMEM);
    cudaFuncSetAttribute(gemm_out,    cudaFuncAttributeMaxDynamicSharedMemorySize, GEMM_SMEM);

    // launch order: attn at captured ncu index 3
    ln2_kernel<<<2 * (MM / 32), 256, LN_SMEM>>>(q, kv, g_q, b_q, g_kv, b_kv,
                                                qln, kvln);           // 0
    prep_kernel<<<(WELEMS + NN * 32 + 255) / 256, 256>>>(Wq, Wk, Wv, Wo, Wr, rope); // 1

    dim3 g_qkv(4, 256, 3);
    gemm_qkv<<<g_qkv, 128, GEMM_SMEM>>>(qln, kvln, Wr, bq, bk, bv,
                                        Qb, Kb, Vb, rope);            // 2

    attn_kernel<<<NHH * BB * 64, 128, ATTN_SMEM>>>(Qb, Kb, Vb, bt, AO); // 3 <- profiled

    dim3 g_o(4, 256);
    gemm_out<<<g_o, 128, GEMM_SMEM>>>(AO, Wr + 3 * (size_t)CC * CC, bo, out, qln);
}

// round 15
// speedup vs baseline: 1.3253x; 1.0077x over previous
#include <cuda_runtime.h>
#include <math.h>
#include <stdint.h>

// Problem constants
#define BB   8
#define CC   512
#define NN   4096            // H*W
#define MM   (BB*NN)         // 32768 tokens
#define NHH  8
#define DDIM 64
#define EPSV 1e-5f
#define SCALEV 0.125f        // 64^-0.5

#define MODE_PLAIN 0
#define MODE_ROPE  1
#define MODE_OUT   2

// Scratch (device globals; container memory is tight: 5 big buffers, AO aliases kvln)
__device__ float g_big [5][MM*CC];  // 0:qln 1:kvln/AO 2:Q 3:K 4:V
__device__ float g_rope[NN*32*2];   // [n][p][{sin,cos}]
__device__ float g_Wr  [4][CC*CC];  // tf32-rounded weights

// ===========================================================================
// helpers
// ===========================================================================
__device__ __forceinline__ uint32_t smem_u32(const void* p) {
    uint32_t a;
    asm("{ .reg .u64 t; cvta.to.shared.u64 t, %1; cvt.u32.u64 %0, t; }" : "=r"(a) : "l"(p));
    return a;
}
__device__ __forceinline__ float round_tf32(float x) {
    uint32_t r;
    asm("cvt.rna.tf32.f32 %0, %1;" : "=r"(r) : "f"(x));
    return __uint_as_float(r);
}
#define CP_ASYNC16(dst, src) \
    asm volatile("cp.async.cg.shared.global [%0], [%1], 16;" :: "r"(dst), "l"(src))
#define CP_COMMIT() asm volatile("cp.async.commit_group;" ::: "memory")

#define LDMX4(r0, r1, r2, r3, addr) \
    asm volatile("ldmatrix.sync.aligned.m8n8.x4.shared.b16 {%0,%1,%2,%3}, [%4];" \
        : "=r"(r0), "=r"(r1), "=r"(r2), "=r"(r3) : "r"(addr))

#define MMA_TF32(d, a, b0v, b1v) \
    asm volatile("mma.sync.aligned.m16n8k8.row.col.f32.tf32.tf32.f32 " \
        "{%0,%1,%2,%3}, {%4,%5,%6,%7}, {%8,%9}, {%0,%1,%2,%3};" \
        : "+f"((d)[0]), "+f"((d)[1]), "+f"((d)[2]), "+f"((d)[3]) \
        : "r"((a)[0]), "r"((a)[1]), "r"((a)[2]), "r"((a)[3]), "r"(b0v), "r"(b1v))

// SW128 swizzle on a byte offset relative to a 1024B-aligned tile base
#define SWZ(o) ((o) ^ (((o) >> 3) & 0x70))

// ===========================================================================
// Fused LayerNorm (q + kv). 32 positions/block, full-line float4 loads,
// padded [512][33] tile. Output (B*N, C) row-major, tf32-rounded.
// ===========================================================================
#define LN_SMEM (CC * 33 * 4)   // 67584 bytes

__global__ void __launch_bounds__(256) ln2_kernel(
    const float* __restrict__ qx, const float* __restrict__ kvx,
    const float* __restrict__ gq, const float* __restrict__ bq,
    const float* __restrict__ gkv, const float* __restrict__ bkv,
    float* __restrict__ oq, float* __restrict__ okv)
{
    extern __shared__ float tile[];          // [512][33]
    __shared__ float ps[8][33], pq[8][33];
    __shared__ float s_mu[32], s_rs[32];

    int bi = blockIdx.x;
    const float *x, *g, *bb;
    float* out;
    if (bi < MM / 32) { x = qx;  g = gq;  bb = bq;  out = oq; }
    else              { x = kvx; g = gkv; bb = bkv; out = okv; bi -= MM / 32; }

    int m0   = bi * 32;
    int bimg = m0 >> 12;
    int n0   = m0 & (NN - 1);
    const float* xb = x + (size_t)bimg * CC * NN + n0;
    int tid = threadIdx.x;

    #pragma unroll
    for (int u = 0; u < 16; u++) {
        int f = tid + u * 256;
        int c = f >> 3, qd = f & 7;
        float4 v = *(const float4*)(xb + (size_t)c * NN + qd * 4);
        tile[c * 33 + qd * 4 + 0] = v.x;
        tile[c * 33 + qd * 4 + 1] = v.y;
        tile[c * 33 + qd * 4 + 2] = v.z;
        tile[c * 33 + qd * 4 + 3] = v.w;
    }
    __syncthreads();

    {
        int p = tid & 31, w = tid >> 5;
        float sum = 0.f, sq = 0.f;
        #pragma unroll
        for (int i = 0; i < 64; i++) {
            float v = tile[(w + 8 * i) * 33 + p];
            sum += v; sq += v * v;
        }
        ps[w][p] = sum; pq[w][p] = sq;
    }
    __syncthreads();
    if (tid < 32) {
        float s = 0.f, s2 = 0.f;
        #pragma unroll
        for (int j = 0; j < 8; j++) { s += ps[j][tid]; s2 += pq[j][tid]; }
        float mu  = s * (1.f / 512.f);
        float var = s2 * (1.f / 512.f) - mu * mu;
        s_mu[tid] = mu;
        s_rs[tid] = rsqrtf(var + EPSV);
    }
    __syncthreads();

    #pragma unroll
    for (int u = 0; u < 16; u++) {
        int f  = tid + u * 256;
        int pp = f >> 7, c4 = (f & 127) * 4;
        float mu = s_mu[pp], rs = s_rs[pp];
        float4 v;
        v.x = round_tf32((tile[(c4 + 0) * 33 + pp] - mu) * rs * g[c4 + 0] + bb[c4 + 0]);
        v.y = round_tf32((tile[(c4 + 1) * 33 + pp] - mu) * rs * g[c4 + 1] + bb[c4 + 1]);
        v.z = round_tf32((tile[(c4 + 2) * 33 + pp] - mu) * rs * g[c4 + 2] + bb[c4 + 2]);
        v.w = round_tf32((tile[(c4 + 3) * 33 + pp] - mu) * rs * g[c4 + 3] + bb[c4 + 3]);
        *(float4*)(out + (size_t)(m0 + pp) * CC + c4) = v;
    }
}

// ===========================================================================
// prep: weight rounding + RoPE table
// ===========================================================================
#define WELEMS (4 * CC * CC)
__global__ void __launch_bounds__(256) prep_kernel(
    const float* __restrict__ w0, const float* __restrict__ w1,
    const float* __restrict__ w2, const float* __restrict__ w3,
    float* __restrict__ dst, float* __restrict__ rope)
{
    int idx = blockIdx.x * 256 + threadIdx.x;
    if (idx < WELEMS) {
        int m = idx >> 18;
        int o = idx & (CC * CC - 1);
        const float* src = (m == 0) ? w0 : (m == 1) ? w1 : (m == 2) ? w2 : w3;
        dst[idx] = round_tf32(src[o]);
    } else if (idx < WELEMS + NN * 32) {
        int t = idx - WELEMS;
        int n = t >> 5, pp = t & 31;
        float inv = 1.f / powf(10000.f, (float)(2 * pp) / 64.f);
        float ang = (float)n * inv;
        rope[t * 2]     = sinf(ang);
        rope[t * 2 + 1] = cosf(ang);
    }
}

// ===========================================================================
// tf32 tensor-core GEMM core (FROZEN: smem-crossbar-bound at 62% tensor).
// CTA 128x128, 4 warps of 64x64, BK=32, 3-stage cp.async, (128, 2).
// ===========================================================================
#define BM 128
#define BN 128
#define BK 32
#define KITERS 16
#define STAGES 3
#define STAGE_A (BM * BK * 4)                  // 16384
#define STAGE_B (BN * BK * 4)                  // 16384
#define STAGE_BYTES (STAGE_A + STAGE_B)        // 32768
#define GEMM_SMEM (STAGES * STAGE_BYTES)       // 98304  (2 CTAs/SM)
#define TROW 132

__device__ __forceinline__ void gemm_core(
    char* smem,
    const float* __restrict__ A, const float* __restrict__ Wm,
    const float* __restrict__ bias, float* __restrict__ Cout,
    const float* __restrict__ rope, const float* __restrict__ resid,
    int mode, int m0, int n0)
{
    uint32_t sbase = smem_u32(smem);
    int tid  = threadIdx.x;
    int wid  = tid >> 5, lane = tid & 31;
    int wm   = wid & 1,  wn   = wid >> 1;

    const float* Arow = A  + (size_t)m0 * 512;
    const float* Brow = Wm + (size_t)n0 * 512;

    auto load_stage = [&](int kt, int slot) {
        uint32_t st = sbase + slot * STAGE_BYTES;
        int k0 = kt * BK;
        #pragma unroll
        for (int u = 0; u < 8; u++) {
            int f = tid + u * 128;
            int r = f >> 3, q = f & 7;
            CP_ASYNC16(st + SWZ((uint32_t)(r * 128 + q * 16)),
                       Arow + (size_t)r * 512 + k0 + q * 4);
        }
        #pragma unroll
        for (int u = 0; u < 8; u++) {
            int f = tid + u * 128;
            int r = f >> 3, q = f & 7;
            CP_ASYNC16(st + STAGE_A + SWZ((uint32_t)(r * 128 + q * 16)),
                       Brow + (size_t)r * 512 + k0 + q * 4);
        }
        CP_COMMIT();
    };

    float acc[4][8][4];
    #pragma unroll
    for (int mt = 0; mt < 4; mt++)
        #pragma unroll
        for (int nt = 0; nt < 8; nt++)
            #pragma unroll
            for (int j = 0; j < 4; j++) acc[mt][nt][j] = 0.f;

    int a_row  = wm * 64 + (lane & 15);
    int a_kb   = (lane >> 4) << 4;
    int b_row  = wn * 64 + (lane & 7) + ((lane >> 4) & 1) * 8;
    int b_kb   = ((lane >> 3) & 1) << 4;

    load_stage(0, 0);
    load_stage(1, 1);

    uint32_t af[2][4][4], bf[2][4][4];

    for (int kt = 0; kt < KITERS; kt++) {
        int slot = kt - (kt / 3) * 3;
        if (kt < 15) asm volatile("cp.async.wait_group 1;" ::: "memory");
        else         asm volatile("cp.async.wait_group 0;" ::: "memory");
        __syncthreads();

        uint32_t sA = sbase + slot * STAGE_BYTES;
        uint32_t sB = sA + STAGE_A;

        #pragma unroll
        for (int mt = 0; mt < 4; mt++) {
            uint32_t ad = sA + SWZ((uint32_t)((a_row + mt * 16) * 128 + a_kb));
            LDMX4(af[0][mt][0], af[0][mt][1], af[0][mt][2], af[0][mt][3], ad);
        }
        #pragma unroll
        for (int np = 0; np < 4; np++) {
            uint32_t bd = sB + SWZ((uint32_t)((b_row + np * 16) * 128 + b_kb));
            LDMX4(bf[0][np][0], bf[0][np][1], bf[0][np][2], bf[0][np][3], bd);
        }

        #pragma unroll
        for (int ks = 0; ks < 4; ks++) {
            int cur = ks & 1, nxt = cur ^ 1;
            if (ks < 3) {
                #pragma unroll
                for (int mt = 0; mt < 4; mt++) {
                    uint32_t ad = sA + SWZ((uint32_t)((a_row + mt * 16) * 128 + (ks + 1) * 32 + a_kb));
                    LDMX4(af[nxt][mt][0], af[nxt][mt][1], af[nxt][mt][2], af[nxt][mt][3], ad);
                }
                #pragma unroll
                for (int np = 0; np < 4; np++) {
                    uint32_t bd = sB + SWZ((uint32_t)((b_row + np * 16) * 128 + (ks + 1) * 32 + b_kb));
                    LDMX4(bf[nxt][np][0], bf[nxt][np][1], bf[nxt][np][2], bf[nxt][np][3], bd);
                }
            }
            #pragma unroll
            for (int mt = 0; mt < 4; mt++)
                #pragma unroll
                for (int np = 0; np < 4; np++) {
                    MMA_TF32(acc[mt][2 * np],     af[cur][mt], bf[cur][np][0], bf[cur][np][1]);
                    MMA_TF32(acc[mt][2 * np + 1], af[cur][mt], bf[cur][np][2], bf[cur][np][3]);
                }
        }

        if (kt <= 13) {
            int kn = kt + 2;
            load_stage(kn, kn - (kn / 3) * 3);
        }
    }

    // ---------------- epilogue ----------------
    int rbase = m0 + wm * 64 + (lane >> 2);
    int cbase = n0 + wn * 64 + 2 * (lane & 3);

    if (mode == MODE_OUT) {
        float* tsm = (float*)smem;                   // [128][TROW]
        int bimg  = m0 >> 12;
        int nbase = m0 & (NN - 1);
        __syncthreads();
        #pragma unroll
        for (int mt = 0; mt < 4; mt++)
            #pragma unroll
            for (int half = 0; half < 2; half++) {
                int r    = rbase + mt * 16 + half * 8;
                int mloc = r - m0;
                const float* rr = resid + (size_t)r * 512;
                #pragma unroll
                for (int nt = 0; nt < 8; nt++) {
                    int c  = cbase + nt * 8;
                    int cl = c - n0;
                    tsm[cl * TROW + mloc] =
                        acc[mt][nt][2 * half]     + bias[c]     + rr[c];
                    tsm[(cl + 1) * TROW + mloc] =
                        acc[mt][nt][2 * half + 1] + bias[c + 1] + rr[c + 1];
                }
            }
        __syncthreads();
        #pragma unroll
        for (int u = 0; u < 32; u++) {
            int f  = tid + u * 128;
            int cl = f >> 5, q = f & 31;
            int cg = n0 + cl;
            float4 v = *(const float4*)&tsm[cl * TROW + q * 4];
            *(float4*)(Cout + (size_t)bimg * CC * NN + (size_t)cg * NN + nbase + q * 4) = v;
        }
        return;
    }

    #pragma unroll
    for (int mt = 0; mt < 4; mt++) {
        int r0 = rbase + mt * 16;
        #pragma unroll
        for (int half = 0; half < 2; half++) {
            int r    = r0 + half * 8;
            int npos = r & (NN - 1);
            const float* rp = rope + (size_t)npos * 64;
            #pragma unroll
            for (int nt = 0; nt < 8; nt++) {
                int   c  = cbase + nt * 8;
                float v0 = acc[mt][nt][2 * half]     + bias[c];
                float v1 = acc[mt][nt][2 * half + 1] + bias[c + 1];

                if (mode == MODE_ROPE) {
                    int   p = (c & 63) >> 1;
                    float s = rp[2 * p], co = rp[2 * p + 1];
                    float x0 = v0, x1 = v1;
                    v0 = x0 * co - x1 * s;
                    v1 = x0 * s  + x1 * co;
                }
                float* op = Cout + (size_t)r * 512 + c;
                op[0] = round_tf32(v0);
                op[1] = round_tf32(v1);
            }
        }
    }
}

__global__ void __launch_bounds__(128, 2) gemm_qkv(
    const float* __restrict__ qln, const float* __restrict__ kvln,
    const float* __restrict__ Wr,
    const float* __restrict__ bq, const float* __restrict__ bk,
    const float* __restrict__ bv,
    float* __restrict__ Qb, float* __restrict__ Kb, float* __restrict__ Vb,
    const float* __restrict__ rope)
{
    extern __shared__ char smem[];
    int z = blockIdx.z;
    const float* A    = (z == 0) ? qln : kvln;
    const float* Wm   = Wr + (size_t)z * CC * CC;
    const float* bias = (z == 0) ? bq : (z == 1) ? bk : bv;
    float*       Cout = (z == 0) ? Qb : (z == 1) ? Kb : Vb;
    int mode = (z == 2) ? MODE_PLAIN : MODE_ROPE;
    gemm_core(smem, A, Wm, bias, Cout, rope, nullptr, mode,
              blockIdx.y * BM, blockIdx.x * BN);
}

__global__ void __launch_bounds__(128, 2) gemm_out(
    const float* __restrict__ A, const float* __restrict__ Wm,
    const float* __restrict__ bias, float* __restrict__ Cout,
    const float* __restrict__ resid)
{
    extern __shared__ char smem[];
    gemm_core(smem, A, Wm, bias, Cout, nullptr, resid, MODE_OUT,
              blockIdx.y * BM, blockIdx.x * BN);
}

// ===========================================================================
// Tensor-core window attention. One block per (head, window), Ws=64, D=64,
// 128 threads / 4 warps, 2x2 of 32x32 warp tiles, mma.sync tf32 both phases.
// P buffer ALIASES the Q buffer (Q dead after phase 1; guarded by a barrier)
// -> smem 50176 B; with __launch_bounds__(128,4) -> 4 CTAs/SM (was 3), which
// is the fix for the measured latency-bound profile (occ 17.9%, issue 18.6%).
// ===========================================================================
#define AQ_OFF  0                // Q, then P after phase 1
#define AK_OFF  16384
#define AV_OFF  32768            // Vt: 64 rows x 272B = 17408
#define ATTN_SMEM (32768 + 17408)   // 50176
#define VROW 272

__global__ void __launch_bounds__(128, 4) attn_kernel(
    const float* __restrict__ Q, const float* __restrict__ K,
    const float* __restrict__ V, const float* __restrict__ bt,
    float* __restrict__ O)
{
    extern __shared__ char asm_[];
    uint32_t sb = smem_u32(asm_);
    __shared__ float tb[232];

    int bi  = blockIdx.x;
    int h   = bi >> 9;
    int rem = bi & 511;
    int b   = rem >> 6;
    int hn  = (rem >> 3) & 7;   // window row
    int wwi = rem & 7;          // window col
    int tid = threadIdx.x;
    int wid = tid >> 5, lane = tid & 31;
    int wm  = wid & 1, wn = wid >> 1;   // 2x2 warp grid

    for (int t = tid; t < 225; t += 128) tb[t] = bt[t * NHH + h];

    size_t base = ((size_t)b * NN) * CC + (size_t)h * DDIM;

    // ---- load Q, K (dq-fastest; swizzled 2-chunk layout) ----
    #pragma unroll
    for (int u = 0; u < 8; u++) {
        int f = tid + u * 128;
        int s = f >> 4, dq = f & 15;
        int th = s >> 3, tw = s & 7;
        int n  = (hn * 8 + th) * 64 + wwi * 8 + tw;
        size_t ga = base + (size_t)n * CC + dq * 4;
        uint32_t off = (uint32_t)((dq >> 3) * 8192 + SWZ(s * 128 + (dq & 7) * 16));
        *(float4*)(asm_ + AQ_OFF + off) = *(const float4*)(Q + ga);
        *(float4*)(asm_ + AK_OFF + off) = *(const float4*)(K + ga);
    }
    // ---- load V transposed (s-fastest to avoid store conflicts) ----
    #pragma unroll
    for (int u = 0; u < 8; u++) {
        int f = tid + u * 128;
        int s = f & 63, dq = f >> 6;
        int th = s >> 3, tw = s & 7;
        int n  = (hn * 8 + th) * 64 + wwi * 8 + tw;
        float4 v = *(const float4*)(V + base + (size_t)n * CC + dq * 4);
        float* vt = (float*)(asm_ + AV_OFF);
        vt[(dq * 4 + 0) * (VROW / 4) + s] = v.x;
        vt[(dq * 4 + 1) * (VROW / 4) + s] = v.y;
        vt[(dq * 4 + 2) * (VROW / 4) + s] = v.z;
        vt[(dq * 4 + 3) * (VROW / 4) + s] = v.w;
    }
    __syncthreads();

    int a_row = wm * 32 + (lane & 15);               // + mt*16
    int a_kb  = (lane >> 4) << 4;
    int b_row = wn * 32 + (lane & 7) + ((lane >> 4) & 1) * 8;   // + np*16
    int b_kb  = ((lane >> 3) & 1) << 4;

    // ---- phase 1: S = Q K^T ----
    float acc[2][4][4];
    #pragma unroll
    for (int mt = 0; mt < 2; mt++)
        #pragma unroll
        for (int nt = 0; nt < 4; nt++)
            #pragma unroll
            for (int j = 0; j < 4; j++) acc[mt][nt][j] = 0.f;

    #pragma unroll
    for (int ks = 0; ks < 8; ks++) {
        uint32_t kc = (uint32_t)(ks >> 2) * 8192;
        uint32_t kb = (uint32_t)(ks & 3) * 32;
        uint32_t af[2][4], bf[2][4];
        #pragma unroll
        for (int mt = 0; mt < 2; mt++) {
            uint32_t ad = sb + AQ_OFF + kc + SWZ((uint32_t)((a_row + mt * 16) * 128 + kb + a_kb));
            LDMX4(af[mt][0], af[mt][1], af[mt][2], af[mt][3], ad);
        }
        #pragma unroll
        for (int np = 0; np < 2; np++) {
            uint32_t bd = sb + AK_OFF + kc + SWZ((uint32_t)((b_row + np * 16) * 128 + kb + b_kb));
            LDMX4(bf[np][0], bf[np][1], bf[np][2], bf[np][3], bd);
        }
        #pragma unroll
        for (int mt = 0; mt < 2; mt++)
            #pragma unroll
            for (int np = 0; np < 2; np++) {
                MMA_TF32(acc[mt][2 * np],     af[mt], bf[np][0], bf[np][1]);
                MMA_TF32(acc[mt][2 * np + 1], af[mt], bf[np][2], bf[np][3]);
            }
    }

    // All warps finished reading Q before P overwrites it
    __syncthreads();

    // ---- scale + rel-pos bias -> P buffer (aliases Q region) ----
    {
        float* pbuf = (float*)(asm_ + AQ_OFF);
        int rb = wm * 32 + (lane >> 2);
        int cb = wn * 32 + 2 * (lane & 3);
        #pragma unroll
        for (int mt = 0; mt < 2; mt++)
            #pragma unroll
            for (int half = 0; half < 2; half++) {
                int r  = rb + mt * 16 + half * 8;
                int ih = r >> 3, iw = r & 7;
                #pragma unroll
                for (int nt = 0; nt < 4; nt++) {
                    int c = cb + nt * 8;
                    uint32_t off = (uint32_t)((c >> 5) * 8192 + SWZ(r * 128 + (c & 31) * 4));
                    float* dst = (float*)((char*)pbuf + off);
                    int j0h = c >> 3, j0w = c & 7;
                    int j1h = (c + 1) >> 3, j1w = (c + 1) & 7;
                    dst[0] = acc[mt][nt][2 * half]     * SCALEV + tb[(ih - j0h + 7) * 15 + (iw - j0w + 7)];
                    dst[1] = acc[mt][nt][2 * half + 1] * SCALEV + tb[(ih - j1h + 7) * 15 + (iw - j1w + 7)];
                }
            }
    }
    __syncthreads();

    // ---- softmax on P (64 rows x 2 lanes, 32 cols each) ----
    {
        float* pbuf = (float*)(asm_ + AQ_OFF);
        int r = tid >> 1, cg = tid & 1;
        char* rowb = (char*)pbuf + cg * 8192;
        float v[32];
        #pragma unroll
        for (int j = 0; j < 32; j++)
            v[j] = *(float*)(rowb + SWZ((uint32_t)(r * 128 + j * 4)));
        float mx = v[0];
        #pragma unroll
        for (int j = 1; j < 32; j++) mx = fmaxf(mx, v[j]);
        mx = fmaxf(mx, __shfl_xor_sync(0xffffffffu, mx, 1));
        float sum = 0.f;
        #pragma unroll
        for (int j = 0; j < 32; j++) { v[j] = __expf(v[j] - mx); sum += v[j]; }
        sum += __shfl_xor_sync(0xffffffffu, sum, 1);
        float inv = 1.f / sum;
        #pragma unroll
        for (int j = 0; j < 32; j++)
            *(float*)(rowb + SWZ((uint32_t)(r * 128 + j * 4))) = round_tf32(v[j] * inv);
    }
    __syncthreads();

    // ---- phase 2: O = P V ----
    float oacc[2][4][4];
    #pragma unroll
    for (int mt = 0; mt < 2; mt++)
        #pragma unroll
        for (int nt = 0; nt < 4; nt++)
            #pragma unroll
            for (int j = 0; j < 4; j++) oacc[mt][nt][j] = 0.f;

    #pragma unroll
    for (int ks = 0; ks < 8; ks++) {
        uint32_t kc = (uint32_t)(ks >> 2) * 8192;
        uint32_t kb = (uint32_t)(ks & 3) * 32;
        uint32_t af[2][4], bf[2][4];
        #pragma unroll
        for (int mt = 0; mt < 2; mt++) {
            uint32_t ad = sb + AQ_OFF + kc + SWZ((uint32_t)((a_row + mt * 16) * 128 + kb + a_kb));
            LDMX4(af[mt][0], af[mt][1], af[mt][2], af[mt][3], ad);
        }
        #pragma unroll
        for (int np = 0; np < 2; np++) {
            uint32_t bd = sb + AV_OFF
                        + (uint32_t)(b_row + np * 16) * VROW
                        + (uint32_t)(ks * 32) + (uint32_t)b_kb;
            LDMX4(bf[np][0], bf[np][1], bf[np][2], bf[np][3], bd);
        }
        #pragma unroll
        for (int mt = 0; mt < 2; mt++)
            #pragma unroll
            for (int np = 0; np < 2; np++) {
                MMA_TF32(oacc[mt][2 * np],     af[mt], bf[np][0], bf[np][1]);
                MMA_TF32(oacc[mt][2 * np + 1], af[mt], bf[np][2], bf[np][3]);
            }
    }

    // ---- store O (tf32-rounded; feeds O-projection GEMM) ----
    {
        int rb = wm * 32 + (lane >> 2);
        int cb = wn * 32 + 2 * (lane & 3);
        #pragma unroll
        for (int mt = 0; mt < 2; mt++)
            #pragma unroll
            for (int half = 0; half < 2; half++) {
                int s  = rb + mt * 16 + half * 8;
                int th = s >> 3, tw = s & 7;
                int n  = (hn * 8 + th) * 64 + wwi * 8 + tw;
                float* op = O + base + (size_t)n * CC;
                #pragma unroll
                for (int nt = 0; nt < 4; nt++) {
                    int c = cb + nt * 8;
                    op[c]     = round_tf32(oacc[mt][nt][2 * half]);
                    op[c + 1] = round_tf32(oacc[mt][nt][2 * half + 1]);
                }
            }
    }
}

// ===========================================================================
extern "C" void kernel_launch(void* const* d_in, const int* in_sizes, int n_in,
                              void* d_out, int out_size)
{
    const float* q    = (const float*)d_in[0];
    const float* kv   = (const float*)d_in[1];
    const float* g_q  = (const float*)d_in[2];
    const float* b_q  = (const float*)d_in[3];
    const float* g_kv = (const float*)d_in[4];
    const float* b_kv = (const float*)d_in[5];
    const float* Wq   = (const float*)d_in[6];
    const float* bq   = (const float*)d_in[7];
    const float* Wk   = (const float*)d_in[8];
    const float* bk   = (const float*)d_in[9];
    const float* Wv   = (const float*)d_in[10];
    const float* bv   = (const float*)d_in[11];
    const float* Wo   = (const float*)d_in[12];
    const float* bo   = (const float*)d_in[13];
    const float* bt   = (const float*)d_in[14];
    float* out = (float*)d_out;

    void *p_big, *p_rope, *p_Wr;
    cudaGetSymbolAddress(&p_big,  g_big);
    cudaGetSymbolAddress(&p_rope, g_rope);
    cudaGetSymbolAddress(&p_Wr,   g_Wr);

    float* qln  = (float*)p_big + 0 * (size_t)MM * CC;
    float* kvln = (float*)p_big + 1 * (size_t)MM * CC;
    float* Qb   = (float*)p_big + 2 * (size_t)MM * CC;
    float* Kb   = (float*)p_big + 3 * (size_t)MM * CC;
    float* Vb   = (float*)p_big + 4 * (size_t)MM * CC;
    float* AO   = kvln;                 // aliased: kvln dead after V GEMM
    float* Wr   = (float*)p_Wr;
    float* rope = (float*)p_rope;

    cudaFuncSetAttribute(attn_kernel, cudaFuncAttributeMaxDynamicSharedMemorySize, ATTN_SMEM);
    cudaFuncSetAttribute(ln2_kernel,  cudaFuncAttributeMaxDynamicSharedMemorySize, LN_SMEM);
    cudaFuncSetAttribute(gemm_qkv,    cudaFuncAttributeMaxDynamicSharedMemorySize, GEMM_SMEM);
    cudaFuncSetAttribute(gemm_out,    cudaFuncAttributeMaxDynamicSharedMemorySize, GEMM_SMEM);

    // launch order: attn at captured ncu index 3
    ln2_kernel<<<2 * (MM / 32), 256, LN_SMEM>>>(q, kv, g_q, b_q, g_kv, b_kv,
                                                qln, kvln);           // 0
    prep_kernel<<<(WELEMS + NN * 32 + 255) / 256, 256>>>(Wq, Wk, Wv, Wo, Wr, rope); // 1

    dim3 g_qkv(4, 256, 3);
    gemm_qkv<<<g_qkv, 128, GEMM_SMEM>>>(qln, kvln, Wr, bq, bk, bv,
                                        Qb, Kb, Vb, rope);            // 2

    attn_kernel<<<NHH * BB * 64, 128, ATTN_SMEM>>>(Qb, Kb, Vb, bt, AO); // 3 <- profiled

    dim3 g_o(4, 256);
    gemm_out<<<g_o, 128, GEMM_SMEM>>>(AO, Wr + 3 * (size_t)CC * CC, bo, out, qln);
}

// round 16
// speedup vs baseline: 1.3682x; 1.0323x over previous
#include <cuda_runtime.h>
#include <math.h>
#include <stdint.h>

// Problem constants
#define BB   8
#define CC   512
#define NN   4096            // H*W
#define MM   (BB*NN)         // 32768 tokens
#define NHH  8
#define DDIM 64
#define EPSV 1e-5f
#define SCALEV 0.125f        // 64^-0.5

#define MODE_PLAIN 0
#define MODE_ROPE  1
#define MODE_OUT   2

// Scratch (device globals; container memory is tight: 5 big buffers, AO aliases kvln)
__device__ float g_big [5][MM*CC];  // 0:qln 1:kvln/AO 2:Q 3:K 4:V
__device__ float g_rope[NN*32*2];   // [n][p][{sin,cos}]
__device__ float g_Wr  [4][CC*CC];  // tf32-rounded weights

// ===========================================================================
// helpers
// ===========================================================================
__device__ __forceinline__ uint32_t smem_u32(const void* p) {
    uint32_t a;
    asm("{ .reg .u64 t; cvta.to.shared.u64 t, %1; cvt.u32.u64 %0, t; }" : "=r"(a) : "l"(p));
    return a;
}
__device__ __forceinline__ float round_tf32(float x) {
    uint32_t r;
    asm("cvt.rna.tf32.f32 %0, %1;" : "=r"(r) : "f"(x));
    return __uint_as_float(r);
}
#define CP_ASYNC16(dst, src) \
    asm volatile("cp.async.cg.shared.global [%0], [%1], 16;" :: "r"(dst), "l"(src))
#define CP_COMMIT() asm volatile("cp.async.commit_group;" ::: "memory")

#define LDMX4(r0, r1, r2, r3, addr) \
    asm volatile("ldmatrix.sync.aligned.m8n8.x4.shared.b16 {%0,%1,%2,%3}, [%4];" \
        : "=r"(r0), "=r"(r1), "=r"(r2), "=r"(r3) : "r"(addr))

#define MMA_TF32(d, a, b0v, b1v) \
    asm volatile("mma.sync.aligned.m16n8k8.row.col.f32.tf32.tf32.f32 " \
        "{%0,%1,%2,%3}, {%4,%5,%6,%7}, {%8,%9}, {%0,%1,%2,%3};" \
        : "+f"((d)[0]), "+f"((d)[1]), "+f"((d)[2]), "+f"((d)[3]) \
        : "r"((a)[0]), "r"((a)[1]), "r"((a)[2]), "r"((a)[3]), "r"(b0v), "r"(b1v))

// SW128 swizzle on a byte offset relative to a 1024B-aligned tile base
#define SWZ(o) ((o) ^ (((o) >> 3) & 0x70))

// ===========================================================================
// Fused LayerNorm (q + kv). 32 positions/block, full-line float4 loads,
// padded [512][33] tile. Output (B*N, C) row-major, tf32-rounded.
// ===========================================================================
#define LN_SMEM (CC * 33 * 4)   // 67584 bytes

__global__ void __launch_bounds__(256) ln2_kernel(
    const float* __restrict__ qx, const float* __restrict__ kvx,
    const float* __restrict__ gq, const float* __restrict__ bq,
    const float* __restrict__ gkv, const float* __restrict__ bkv,
    float* __restrict__ oq, float* __restrict__ okv)
{
    extern __shared__ float tile[];          // [512][33]
    __shared__ float ps[8][33], pq[8][33];
    __shared__ float s_mu[32], s_rs[32];

    int bi = blockIdx.x;
    const float *x, *g, *bb;
    float* out;
    if (bi < MM / 32) { x = qx;  g = gq;  bb = bq;  out = oq; }
    else              { x = kvx; g = gkv; bb = bkv; out = okv; bi -= MM / 32; }

    int m0   = bi * 32;
    int bimg = m0 >> 12;
    int n0   = m0 & (NN - 1);
    const float* xb = x + (size_t)bimg * CC * NN + n0;
    int tid = threadIdx.x;

    #pragma unroll
    for (int u = 0; u < 16; u++) {
        int f = tid + u * 256;
        int c = f >> 3, qd = f & 7;
        float4 v = *(const float4*)(xb + (size_t)c * NN + qd * 4);
        tile[c * 33 + qd * 4 + 0] = v.x;
        tile[c * 33 + qd * 4 + 1] = v.y;
        tile[c * 33 + qd * 4 + 2] = v.z;
        tile[c * 33 + qd * 4 + 3] = v.w;
    }
    __syncthreads();

    {
        int p = tid & 31, w = tid >> 5;
        float sum = 0.f, sq = 0.f;
        #pragma unroll
        for (int i = 0; i < 64; i++) {
            float v = tile[(w + 8 * i) * 33 + p];
            sum += v; sq += v * v;
        }
        ps[w][p] = sum; pq[w][p] = sq;
    }
    __syncthreads();
    if (tid < 32) {
        float s = 0.f, s2 = 0.f;
        #pragma unroll
        for (int j = 0; j < 8; j++) { s += ps[j][tid]; s2 += pq[j][tid]; }
        float mu  = s * (1.f / 512.f);
        float var = s2 * (1.f / 512.f) - mu * mu;
        s_mu[tid] = mu;
        s_rs[tid] = rsqrtf(var + EPSV);
    }
    __syncthreads();

    #pragma unroll
    for (int u = 0; u < 16; u++) {
        int f  = tid + u * 256;
        int pp = f >> 7, c4 = (f & 127) * 4;
        float mu = s_mu[pp], rs = s_rs[pp];
        float4 v;
        v.x = round_tf32((tile[(c4 + 0) * 33 + pp] - mu) * rs * g[c4 + 0] + bb[c4 + 0]);
        v.y = round_tf32((tile[(c4 + 1) * 33 + pp] - mu) * rs * g[c4 + 1] + bb[c4 + 1]);
        v.z = round_tf32((tile[(c4 + 2) * 33 + pp] - mu) * rs * g[c4 + 2] + bb[c4 + 2]);
        v.w = round_tf32((tile[(c4 + 3) * 33 + pp] - mu) * rs * g[c4 + 3] + bb[c4 + 3]);
        *(float4*)(out + (size_t)(m0 + pp) * CC + c4) = v;
    }
}

// ===========================================================================
// prep: weight rounding + RoPE table
// ===========================================================================
#define WELEMS (4 * CC * CC)
__global__ void __launch_bounds__(256) prep_kernel(
    const float* __restrict__ w0, const float* __restrict__ w1,
    const float* __restrict__ w2, const float* __restrict__ w3,
    float* __restrict__ dst, float* __restrict__ rope)
{
    int idx = blockIdx.x * 256 + threadIdx.x;
    if (idx < WELEMS) {
        int m = idx >> 18;
        int o = idx & (CC * CC - 1);
        const float* src = (m == 0) ? w0 : (m == 1) ? w1 : (m == 2) ? w2 : w3;
        dst[idx] = round_tf32(src[o]);
    } else if (idx < WELEMS + NN * 32) {
        int t = idx - WELEMS;
        int n = t >> 5, pp = t & 31;
        float inv = 1.f / powf(10000.f, (float)(2 * pp) / 64.f);
        float ang = (float)n * inv;
        rope[t * 2]     = sinf(ang);
        rope[t * 2 + 1] = cosf(ang);
    }
}

// ===========================================================================
// tf32 tensor-core GEMM core (FROZEN: smem-crossbar-bound at 62% tensor).
// CTA 128x128, 4 warps of 64x64, BK=32, 3-stage cp.async, (128, 2).
// ===========================================================================
#define BM 128
#define BN 128
#define BK 32
#define KITERS 16
#define STAGES 3
#define STAGE_A (BM * BK * 4)                  // 16384
#define STAGE_B (BN * BK * 4)                  // 16384
#define STAGE_BYTES (STAGE_A + STAGE_B)        // 32768
#define GEMM_SMEM (STAGES * STAGE_BYTES)       // 98304  (2 CTAs/SM)
#define TROW 132

__device__ __forceinline__ void gemm_core(
    char* smem,
    const float* __restrict__ A, const float* __restrict__ Wm,
    const float* __restrict__ bias, float* __restrict__ Cout,
    const float* __restrict__ rope, const float* __restrict__ resid,
    int mode, int m0, int n0)
{
    uint32_t sbase = smem_u32(smem);
    int tid  = threadIdx.x;
    int wid  = tid >> 5, lane = tid & 31;
    int wm   = wid & 1,  wn   = wid >> 1;

    const float* Arow = A  + (size_t)m0 * 512;
    const float* Brow = Wm + (size_t)n0 * 512;

    auto load_stage = [&](int kt, int slot) {
        uint32_t st = sbase + slot * STAGE_BYTES;
        int k0 = kt * BK;
        #pragma unroll
        for (int u = 0; u < 8; u++) {
            int f = tid + u * 128;
            int r = f >> 3, q = f & 7;
            CP_ASYNC16(st + SWZ((uint32_t)(r * 128 + q * 16)),
                       Arow + (size_t)r * 512 + k0 + q * 4);
        }
        #pragma unroll
        for (int u = 0; u < 8; u++) {
            int f = tid + u * 128;
            int r = f >> 3, q = f & 7;
            CP_ASYNC16(st + STAGE_A + SWZ((uint32_t)(r * 128 + q * 16)),
                       Brow + (size_t)r * 512 + k0 + q * 4);
        }
        CP_COMMIT();
    };

    float acc[4][8][4];
    #pragma unroll
    for (int mt = 0; mt < 4; mt++)
        #pragma unroll
        for (int nt = 0; nt < 8; nt++)
            #pragma unroll
            for (int j = 0; j < 4; j++) acc[mt][nt][j] = 0.f;

    int a_row  = wm * 64 + (lane & 15);
    int a_kb   = (lane >> 4) << 4;
    int b_row  = wn * 64 + (lane & 7) + ((lane >> 4) & 1) * 8;
    int b_kb   = ((lane >> 3) & 1) << 4;

    load_stage(0, 0);
    load_stage(1, 1);

    uint32_t af[2][4][4], bf[2][4][4];

    for (int kt = 0; kt < KITERS; kt++) {
        int slot = kt - (kt / 3) * 3;
        if (kt < 15) asm volatile("cp.async.wait_group 1;" ::: "memory");
        else         asm volatile("cp.async.wait_group 0;" ::: "memory");
        __syncthreads();

        uint32_t sA = sbase + slot * STAGE_BYTES;
        uint32_t sB = sA + STAGE_A;

        #pragma unroll
        for (int mt = 0; mt < 4; mt++) {
            uint32_t ad = sA + SWZ((uint32_t)((a_row + mt * 16) * 128 + a_kb));
            LDMX4(af[0][mt][0], af[0][mt][1], af[0][mt][2], af[0][mt][3], ad);
        }
        #pragma unroll
        for (int np = 0; np < 4; np++) {
            uint32_t bd = sB + SWZ((uint32_t)((b_row + np * 16) * 128 + b_kb));
            LDMX4(bf[0][np][0], bf[0][np][1], bf[0][np][2], bf[0][np][3], bd);
        }

        #pragma unroll
        for (int ks = 0; ks < 4; ks++) {
            int cur = ks & 1, nxt = cur ^ 1;
            if (ks < 3) {
                #pragma unroll
                for (int mt = 0; mt < 4; mt++) {
                    uint32_t ad = sA + SWZ((uint32_t)((a_row + mt * 16) * 128 + (ks + 1) * 32 + a_kb));
                    LDMX4(af[nxt][mt][0], af[nxt][mt][1], af[nxt][mt][2], af[nxt][mt][3], ad);
                }
                #pragma unroll
                for (int np = 0; np < 4; np++) {
                    uint32_t bd = sB + SWZ((uint32_t)((b_row + np * 16) * 128 + (ks + 1) * 32 + b_kb));
                    LDMX4(bf[nxt][np][0], bf[nxt][np][1], bf[nxt][np][2], bf[nxt][np][3], bd);
                }
            }
            #pragma unroll
            for (int mt = 0; mt < 4; mt++)
                #pragma unroll
                for (int np = 0; np < 4; np++) {
                    MMA_TF32(acc[mt][2 * np],     af[cur][mt], bf[cur][np][0], bf[cur][np][1]);
                    MMA_TF32(acc[mt][2 * np + 1], af[cur][mt], bf[cur][np][2], bf[cur][np][3]);
                }
        }

        if (kt <= 13) {
            int kn = kt + 2;
            load_stage(kn, kn - (kn / 3) * 3);
        }
    }

    // ---------------- epilogue ----------------
    int rbase = m0 + wm * 64 + (lane >> 2);
    int cbase = n0 + wn * 64 + 2 * (lane & 3);

    if (mode == MODE_OUT) {
        float* tsm = (float*)smem;                   // [128][TROW]
        int bimg  = m0 >> 12;
        int nbase = m0 & (NN - 1);
        __syncthreads();
        #pragma unroll
        for (int mt = 0; mt < 4; mt++)
            #pragma unroll
            for (int half = 0; half < 2; half++) {
                int r    = rbase + mt * 16 + half * 8;
                int mloc = r - m0;
                const float* rr = resid + (size_t)r * 512;
                #pragma unroll
                for (int nt = 0; nt < 8; nt++) {
                    int c  = cbase + nt * 8;
                    int cl = c - n0;
                    tsm[cl * TROW + mloc] =
                        acc[mt][nt][2 * half]     + bias[c]     + rr[c];
                    tsm[(cl + 1) * TROW + mloc] =
                        acc[mt][nt][2 * half + 1] + bias[c + 1] + rr[c + 1];
                }
            }
        __syncthreads();
        #pragma unroll
        for (int u = 0; u < 32; u++) {
            int f  = tid + u * 128;
            int cl = f >> 5, q = f & 31;
            int cg = n0 + cl;
            float4 v = *(const float4*)&tsm[cl * TROW + q * 4];
            *(float4*)(Cout + (size_t)bimg * CC * NN + (size_t)cg * NN + nbase + q * 4) = v;
        }
        return;
    }

    #pragma unroll
    for (int mt = 0; mt < 4; mt++) {
        int r0 = rbase + mt * 16;
        #pragma unroll
        for (int half = 0; half < 2; half++) {
            int r    = r0 + half * 8;
            int npos = r & (NN - 1);
            const float* rp = rope + (size_t)npos * 64;
            #pragma unroll
            for (int nt = 0; nt < 8; nt++) {
                int   c  = cbase + nt * 8;
                float v0 = acc[mt][nt][2 * half]     + bias[c];
                float v1 = acc[mt][nt][2 * half + 1] + bias[c + 1];

                if (mode == MODE_ROPE) {
                    int   p = (c & 63) >> 1;
                    float s = rp[2 * p], co = rp[2 * p + 1];
                    float x0 = v0, x1 = v1;
                    v0 = x0 * co - x1 * s;
                    v1 = x0 * s  + x1 * co;
                }
                float* op = Cout + (size_t)r * 512 + c;
                op[0] = round_tf32(v0);
                op[1] = round_tf32(v1);
            }
        }
    }
}

__global__ void __launch_bounds__(128, 2) gemm_qkv(
    const float* __restrict__ qln, const float* __restrict__ kvln,
    const float* __restrict__ Wr,
    const float* __restrict__ bq, const float* __restrict__ bk,
    const float* __restrict__ bv,
    float* __restrict__ Qb, float* __restrict__ Kb, float* __restrict__ Vb,
    const float* __restrict__ rope)
{
    extern __shared__ char smem[];
    int z = blockIdx.z;
    const float* A    = (z == 0) ? qln : kvln;
    const float* Wm   = Wr + (size_t)z * CC * CC;
    const float* bias = (z == 0) ? bq : (z == 1) ? bk : bv;
    float*       Cout = (z == 0) ? Qb : (z == 1) ? Kb : Vb;
    int mode = (z == 2) ? MODE_PLAIN : MODE_ROPE;
    gemm_core(smem, A, Wm, bias, Cout, rope, nullptr, mode,
              blockIdx.y * BM, blockIdx.x * BN);
}

__global__ void __launch_bounds__(128, 2) gemm_out(
    const float* __restrict__ A, const float* __restrict__ Wm,
    const float* __restrict__ bias, float* __restrict__ Cout,
    const float* __restrict__ resid)
{
    extern __shared__ char smem[];
    gemm_core(smem, A, Wm, bias, Cout, nullptr, resid, MODE_OUT,
              blockIdx.y * BM, blockIdx.x * BN);
}

// ===========================================================================
// Tensor-core window attention. One block per (head, window), Ws=64, D=64,
// 128 threads / 4 warps, 2x2 of 32x32 warp tiles, mma.sync tf32 both phases.
// Load phase: Q/K via cp.async (no register round-trip, deep MLP); V's
// LDG+transpose overlaps with the in-flight bulk copies. P aliases Q.
// smem 50176 B, __launch_bounds__(128,4) -> 4 CTAs/SM.
// ===========================================================================
#define AQ_OFF  0                // Q, then P after phase 1
#define AK_OFF  16384
#define AV_OFF  32768            // Vt: 64 rows x 272B = 17408
#define ATTN_SMEM (32768 + 17408)   // 50176
#define VROW 272

__global__ void __launch_bounds__(128, 4) attn_kernel(
    const float* __restrict__ Q, const float* __restrict__ K,
    const float* __restrict__ V, const float* __restrict__ bt,
    float* __restrict__ O)
{
    extern __shared__ char asm_[];
    uint32_t sb = smem_u32(asm_);
    __shared__ float tb[232];

    int bi  = blockIdx.x;
    int h   = bi >> 9;
    int rem = bi & 511;
    int b   = rem >> 6;
    int hn  = (rem >> 3) & 7;   // window row
    int wwi = rem & 7;          // window col
    int tid = threadIdx.x;
    int wid = tid >> 5, lane = tid & 31;
    int wm  = wid & 1, wn = wid >> 1;   // 2x2 warp grid

    size_t base = ((size_t)b * NN) * CC + (size_t)h * DDIM;

    // ---- Q, K via cp.async into swizzled 2-chunk layouts (issued first) ----
    #pragma unroll
    for (int u = 0; u < 8; u++) {
        int f = tid + u * 128;
        int s = f >> 4, dq = f & 15;
        int th = s >> 3, tw = s & 7;
        int n  = (hn * 8 + th) * 64 + wwi * 8 + tw;
        size_t ga = base + (size_t)n * CC + dq * 4;
        uint32_t off = (uint32_t)((dq >> 3) * 8192 + SWZ(s * 128 + (dq & 7) * 16));
        CP_ASYNC16(sb + AQ_OFF + off, Q + ga);
        CP_ASYNC16(sb + AK_OFF + off, K + ga);
    }
    CP_COMMIT();

    // bias table + V transpose overlap with the in-flight cp.asyncs
    for (int t = tid; t < 225; t += 128) tb[t] = bt[t * NHH + h];

    #pragma unroll
    for (int u = 0; u < 8; u++) {
        int f = tid + u * 128;
        int s = f & 63, dq = f >> 6;
        int th = s >> 3, tw = s & 7;
        int n  = (hn * 8 + th) * 64 + wwi * 8 + tw;
        float4 v = *(const float4*)(V + base + (size_t)n * CC + dq * 4);
        float* vt = (float*)(asm_ + AV_OFF);
        vt[(dq * 4 + 0) * (VROW / 4) + s] = v.x;
        vt[(dq * 4 + 1) * (VROW / 4) + s] = v.y;
        vt[(dq * 4 + 2) * (VROW / 4) + s] = v.z;
        vt[(dq * 4 + 3) * (VROW / 4) + s] = v.w;
    }
    asm volatile("cp.async.wait_group 0;" ::: "memory");
    __syncthreads();

    int a_row = wm * 32 + (lane & 15);               // + mt*16
    int a_kb  = (lane >> 4) << 4;
    int b_row = wn * 32 + (lane & 7) + ((lane >> 4) & 1) * 8;   // + np*16
    int b_kb  = ((lane >> 3) & 1) << 4;

    // ---- phase 1: S = Q K^T ----
    float acc[2][4][4];
    #pragma unroll
    for (int mt = 0; mt < 2; mt++)
        #pragma unroll
        for (int nt = 0; nt < 4; nt++)
            #pragma unroll
            for (int j = 0; j < 4; j++) acc[mt][nt][j] = 0.f;

    #pragma unroll
    for (int ks = 0; ks < 8; ks++) {
        uint32_t kc = (uint32_t)(ks >> 2) * 8192;
        uint32_t kb = (uint32_t)(ks & 3) * 32;
        uint32_t af[2][4], bf[2][4];
        #pragma unroll
        for (int mt = 0; mt < 2; mt++) {
            uint32_t ad = sb + AQ_OFF + kc + SWZ((uint32_t)((a_row + mt * 16) * 128 + kb + a_kb));
            LDMX4(af[mt][0], af[mt][1], af[mt][2], af[mt][3], ad);
        }
        #pragma unroll
        for (int np = 0; np < 2; np++) {
            uint32_t bd = sb + AK_OFF + kc + SWZ((uint32_t)((b_row + np * 16) * 128 + kb + b_kb));
            LDMX4(bf[np][0], bf[np][1], bf[np][2], bf[np][3], bd);
        }
        #pragma unroll
        for (int mt = 0; mt < 2; mt++)
            #pragma unroll
            for (int np = 0; np < 2; np++) {
                MMA_TF32(acc[mt][2 * np],     af[mt], bf[np][0], bf[np][1]);
                MMA_TF32(acc[mt][2 * np + 1], af[mt], bf[np][2], bf[np][3]);
            }
    }

    // All warps finished reading Q before P overwrites it
    __syncthreads();

    // ---- scale + rel-pos bias -> P buffer (aliases Q region) ----
    {
        float* pbuf = (float*)(asm_ + AQ_OFF);
        int rb = wm * 32 + (lane >> 2);
        int cb = wn * 32 + 2 * (lane & 3);
        #pragma unroll
        for (int mt = 0; mt < 2; mt++)
            #pragma unroll
            for (int half = 0; half < 2; half++) {
                int r  = rb + mt * 16 + half * 8;
                int ih = r >> 3, iw = r & 7;
                #pragma unroll
                for (int nt = 0; nt < 4; nt++) {
                    int c = cb + nt * 8;
                    uint32_t off = (uint32_t)((c >> 5) * 8192 + SWZ(r * 128 + (c & 31) * 4));
                    float* dst = (float*)((char*)pbuf + off);
                    int j0h = c >> 3, j0w = c & 7;
                    int j1h = (c + 1) >> 3, j1w = (c + 1) & 7;
                    dst[0] = acc[mt][nt][2 * half]     * SCALEV + tb[(ih - j0h + 7) * 15 + (iw - j0w + 7)];
                    dst[1] = acc[mt][nt][2 * half + 1] * SCALEV + tb[(ih - j1h + 7) * 15 + (iw - j1w + 7)];
                }
            }
    }
    __syncthreads();

    // ---- softmax on P (64 rows x 2 lanes, 32 cols each) ----
    {
        float* pbuf = (float*)(asm_ + AQ_OFF);
        int r = tid >> 1, cg = tid & 1;
        char* rowb = (char*)pbuf + cg * 8192;
        float v[32];
        #pragma unroll
        for (int j = 0; j < 32; j++)
            v[j] = *(float*)(rowb + SWZ((uint32_t)(r * 128 + j * 4)));
        float mx = v[0];
        #pragma unroll
        for (int j = 1; j < 32; j++) mx = fmaxf(mx, v[j]);
        mx = fmaxf(mx, __shfl_xor_sync(0xffffffffu, mx, 1));
        float sum = 0.f;
        #pragma unroll
        for (int j = 0; j < 32; j++) { v[j] = __expf(v[j] - mx); sum += v[j]; }
        sum += __shfl_xor_sync(0xffffffffu, sum, 1);
        float inv = 1.f / sum;
        #pragma unroll
        for (int j = 0; j < 32; j++)
            *(float*)(rowb + SWZ((uint32_t)(r * 128 + j * 4))) = round_tf32(v[j] * inv);
    }
    __syncthreads();

    // ---- phase 2: O = P V ----
    float oacc[2][4][4];
    #pragma unroll
    for (int mt = 0; mt < 2; mt++)
        #pragma unroll
        for (int nt = 0; nt < 4; nt++)
            #pragma unroll
            for (int j = 0; j < 4; j++) oacc[mt][nt][j] = 0.f;

    #pragma unroll
    for (int ks = 0; ks < 8; ks++) {
        uint32_t kc = (uint32_t)(ks >> 2) * 8192;
        uint32_t kb = (uint32_t)(ks & 3) * 32;
        uint32_t af[2][4], bf[2][4];
        #pragma unroll
        for (int mt = 0; mt < 2; mt++) {
            uint32_t ad = sb + AQ_OFF + kc + SWZ((uint32_t)((a_row + mt * 16) * 128 + kb + a_kb));
            LDMX4(af[mt][0], af[mt][1], af[mt][2], af[mt][3], ad);
        }
        #pragma unroll
        for (int np = 0; np < 2; np++) {
            uint32_t bd = sb + AV_OFF
                        + (uint32_t)(b_row + np * 16) * VROW
                        + (uint32_t)(ks * 32) + (uint32_t)b_kb;
            LDMX4(bf[np][0], bf[np][1], bf[np][2], bf[np][3], bd);
        }
        #pragma unroll
        for (int mt = 0; mt < 2; mt++)
            #pragma unroll
            for (int np = 0; np < 2; np++) {
                MMA_TF32(oacc[mt][2 * np],     af[mt], bf[np][0], bf[np][1]);
                MMA_TF32(oacc[mt][2 * np + 1], af[mt], bf[np][2], bf[np][3]);
            }
    }

    // ---- store O (tf32-rounded; feeds O-projection GEMM) ----
    {
        int rb = wm * 32 + (lane >> 2);
        int cb = wn * 32 + 2 * (lane & 3);
        #pragma unroll
        for (int mt = 0; mt < 2; mt++)
            #pragma unroll
            for (int half = 0; half < 2; half++) {
                int s  = rb + mt * 16 + half * 8;
                int th = s >> 3, tw = s & 7;
                int n  = (hn * 8 + th) * 64 + wwi * 8 + tw;
                float* op = O + base + (size_t)n * CC;
                #pragma unroll
                for (int nt = 0; nt < 4; nt++) {
                    int c = cb + nt * 8;
                    op[c]     = round_tf32(oacc[mt][nt][2 * half]);
                    op[c + 1] = round_tf32(oacc[mt][nt][2 * half + 1]);
                }
            }
    }
}

// ===========================================================================
extern "C" void kernel_launch(void* const* d_in, const int* in_sizes, int n_in,
                              void* d_out, int out_size)
{
    const float* q    = (const float*)d_in[0];
    const float* kv   = (const float*)d_in[1];
    const float* g_q  = (const float*)d_in[2];
    const float* b_q  = (const float*)d_in[3];
    const float* g_kv = (const float*)d_in[4];
    const float* b_kv = (const float*)d_in[5];
    const float* Wq   = (const float*)d_in[6];
    const float* bq   = (const float*)d_in[7];
    const float* Wk   = (const float*)d_in[8];
    const float* bk   = (const float*)d_in[9];
    const float* Wv   = (const float*)d_in[10];
    const float* bv   = (const float*)d_in[11];
    const float* Wo   = (const float*)d_in[12];
    const float* bo   = (const float*)d_in[13];
    const float* bt   = (const float*)d_in[14];
    float* out = (float*)d_out;

    void *p_big, *p_rope, *p_Wr;
    cudaGetSymbolAddress(&p_big,  g_big);
    cudaGetSymbolAddress(&p_rope, g_rope);
    cudaGetSymbolAddress(&p_Wr,   g_Wr);

    float* qln  = (float*)p_big + 0 * (size_t)MM * CC;
    float* kvln = (float*)p_big + 1 * (size_t)MM * CC;
    float* Qb   = (float*)p_big + 2 * (size_t)MM * CC;
    float* Kb   = (float*)p_big + 3 * (size_t)MM * CC;
    float* Vb   = (float*)p_big + 4 * (size_t)MM * CC;
    float* AO   = kvln;                 // aliased: kvln dead after V GEMM
    float* Wr   = (float*)p_Wr;
    float* rope = (float*)p_rope;

    cudaFuncSetAttribute(attn_kernel, cudaFuncAttributeMaxDynamicSharedMemorySize, ATTN_SMEM);
    cudaFuncSetAttribute(ln2_kernel,  cudaFuncAttributeMaxDynamicSharedMemorySize, LN_SMEM);
    cudaFuncSetAttribute(gemm_qkv,    cudaFuncAttributeMaxDynamicSharedMemorySize, GEMM_SMEM);
    cudaFuncSetAttribute(gemm_out,    cudaFuncAttributeMaxDynamicSharedMemorySize, GEMM_SMEM);

    // launch order: attn at captured ncu index 3
    ln2_kernel<<<2 * (MM / 32), 256, LN_SMEM>>>(q, kv, g_q, b_q, g_kv, b_kv,
                                                qln, kvln);           // 0
    prep_kernel<<<(WELEMS + NN * 32 + 255) / 256, 256>>>(Wq, Wk, Wv, Wo, Wr, rope); // 1

    dim3 g_qkv(4, 256, 3);
    gemm_qkv<<<g_qkv, 128, GEMM_SMEM>>>(qln, kvln, Wr, bq, bk, bv,
                                        Qb, Kb, Vb, rope);            // 2

    attn_kernel<<<NHH * BB * 64, 128, ATTN_SMEM>>>(Qb, Kb, Vb, bt, AO); // 3 <- profiled

    dim3 g_o(4, 256);
    gemm_out<<<g_o, 128, GEMM_SMEM>>>(AO, Wr + 3 * (size_t)CC * CC, bo, out, qln);
}